// round 6
// baseline (speedup 1.0000x reference)
#include <cuda_runtime.h>
#include <cuda_fp16.h>
#include <cstdint>

#define BATCH 32768
#define HD 128
#define OD 32
#define DEPTH 5
typedef uint32_t u32;

// ---- weight tile offsets in g_wt (halves) ----
#define W_ANC_WH  0
#define W_FRAT_WH 98304
#define W_ANC_WI  196608
#define W_FRAT_WI 221184
#define W_UF      245760
#define W_UA      278528
#define W_H2O     311296
__device__ __half g_wt[319488];

__device__ __half g_hAh[DEPTH + 1][BATCH * HD];
__device__ __half g_hAl[DEPTH + 1][BATCH * HD];
__device__ __half g_hFh[DEPTH][BATCH * HD];
__device__ __half g_hFl[DEPTH][BATCH * HD];
__device__ __half g_prh[DEPTH + 1][BATCH * OD];
__device__ __half g_prl[DEPTH + 1][BATCH * OD];

// ===================== helpers =====================
__device__ __forceinline__ u32 smaddr(const void* p) {
    u32 a;
    asm("{ .reg .u64 t; cvta.to.shared.u64 t, %1; cvt.u32.u64 %0, t; }" : "=r"(a) : "l"(p));
    return a;
}
__device__ __forceinline__ void cpa16(u32 d, const void* s) {
    asm volatile("cp.async.cg.shared.global [%0], [%1], 16;" :: "r"(d), "l"(s) : "memory");
}
__device__ __forceinline__ void cpcommit() {
    asm volatile("cp.async.commit_group;" ::: "memory");
}
__device__ __forceinline__ void cpwait0() {
    asm volatile("cp.async.wait_group 0;" ::: "memory");
}
__device__ __forceinline__ void ldm4(u32* r, u32 a) {
    asm volatile("ldmatrix.sync.aligned.m8n8.x4.shared.b16 {%0,%1,%2,%3}, [%4];"
                 : "=r"(r[0]), "=r"(r[1]), "=r"(r[2]), "=r"(r[3]) : "r"(a));
}
__device__ __forceinline__ void mmaf(float* c, const u32* a, const u32* b) {
    asm volatile(
        "mma.sync.aligned.m16n8k16.row.col.f32.f16.f16.f32 "
        "{%0,%1,%2,%3},{%4,%5,%6,%7},{%8,%9},{%0,%1,%2,%3};"
        : "+f"(c[0]), "+f"(c[1]), "+f"(c[2]), "+f"(c[3])
        : "r"(a[0]), "r"(a[1]), "r"(a[2]), "r"(a[3]), "r"(b[0]), "r"(b[1]));
}
__device__ __forceinline__ float fsig(float x)  { return __fdividef(1.0f, 1.0f + __expf(-x)); }
__device__ __forceinline__ float ftanh(float x) { float u = __expf(2.0f * x); return 1.0f - __fdividef(2.0f, u + 1.0f); }
__device__ __forceinline__ void wsplit(float v, __half& h, __half& l) {
    h = __float2half_rn(v);
    l = __float2half_rn(v - __half2float(h));
}

// ---- ldmatrix addressing (validated in R5) ----
__device__ __forceinline__ void ldmA128(u32* r, u32 base, int m0, int lane, int kc) {
    int row = m0 + (lane & 15), c16 = 2 * kc + (lane >> 4);
    ldm4(r, base + (u32)row * 256u + (u32)((c16 ^ (row & 7)) << 4));
}
__device__ __forceinline__ void ldmB128(u32* r, u32 base, int n0, int lane, int kc) {
    int row = n0 + (lane & 7) + ((lane >> 4) << 3), c16 = 2 * kc + ((lane >> 3) & 1);
    ldm4(r, base + (u32)row * 256u + (u32)((c16 ^ (row & 7)) << 4));
}
__device__ __forceinline__ void ldmA32(u32* r, u32 base, int m0, int lane, int kc) {
    int row = m0 + (lane & 15), c4 = 2 * kc + (lane >> 4);
    ldm4(r, base + (u32)row * 64u + (u32)((c4 ^ (row & 3)) << 4));
}
__device__ __forceinline__ void ldmB32(u32* r, u32 base, int n0, int lane, int kc) {
    int row = n0 + (lane & 7) + ((lane >> 4) << 3), c4 = 2 * kc + ((lane >> 3) & 1);
    ldm4(r, base + (u32)row * 64u + (u32)((c4 ^ (row & 3)) << 4));
}
// A fragment (row-major m16k16) loaded straight from global (L2-hot lo planes)
__device__ __forceinline__ void ldgA(u32* r, const __half* __restrict__ base, int pitch,
                                     int rowg, int lane, int kc) {
    const __half* p = base + (size_t)(rowg + (lane >> 2)) * pitch + kc * 16 + (lane & 3) * 2;
    r[0] = *(const u32*)p;
    r[1] = *(const u32*)(p + (size_t)8 * pitch);
    r[2] = *(const u32*)(p + 8);
    r[3] = *(const u32*)(p + (size_t)8 * pitch + 8);
}

// ---- 32x64 warp tile, 3-term hi/lo, one k16 chunk ----
__device__ __forceinline__ void kstep128v2(float (*acc)[4], u32 AH, const __half* Alo,
                                           u32 BH, u32 BL, int m0, int n0, int lane, int kc) {
    u32 a[2][4], al[2][4];
    ldmA128(a[0], AH, m0, lane, kc);        ldmA128(a[1], AH, m0 + 16, lane, kc);
    ldgA(al[0], Alo, 128, m0, lane, kc);    ldgA(al[1], Alo, 128, m0 + 16, lane, kc);
#pragma unroll
    for (int G = 0; G < 4; G++) {
        u32 bh[4], bl[4];
        ldmB128(bh, BH, n0 + G * 16, lane, kc);
        ldmB128(bl, BL, n0 + G * 16, lane, kc);
#pragma unroll
        for (int mf = 0; mf < 2; mf++) {
            float* c0 = acc[mf * 8 + G * 2];
            float* c1 = acc[mf * 8 + G * 2 + 1];
            mmaf(c0, a[mf], bh);     mmaf(c1, a[mf], bh + 2);
            mmaf(c0, a[mf], bl);     mmaf(c1, a[mf], bl + 2);
            mmaf(c0, al[mf], bh);    mmaf(c1, al[mf], bh + 2);
        }
    }
}
__device__ __forceinline__ void kstep32v2(float (*acc)[4], u32 AH, const __half* Alo,
                                          u32 BH, u32 BL, int m0, int n0, int lane, int kc) {
    u32 a[2][4], al[2][4];
    ldmA32(a[0], AH, m0, lane, kc);         ldmA32(a[1], AH, m0 + 16, lane, kc);
    ldgA(al[0], Alo, 32, m0, lane, kc);     ldgA(al[1], Alo, 32, m0 + 16, lane, kc);
#pragma unroll
    for (int G = 0; G < 4; G++) {
        u32 bh[4], bl[4];
        ldmB32(bh, BH, n0 + G * 16, lane, kc);
        ldmB32(bl, BL, n0 + G * 16, lane, kc);
#pragma unroll
        for (int mf = 0; mf < 2; mf++) {
            float* c0 = acc[mf * 8 + G * 2];
            float* c1 = acc[mf * 8 + G * 2 + 1];
            mmaf(c0, a[mf], bh);     mmaf(c1, a[mf], bh + 2);
            mmaf(c0, a[mf], bl);     mmaf(c1, a[mf], bl + 2);
            mmaf(c0, al[mf], bh);    mmaf(c1, al[mf], bh + 2);
        }
    }
}
__device__ __forceinline__ void zacc(float (*acc)[4]) {
#pragma unroll
    for (int f = 0; f < 16; f++)
#pragma unroll
        for (int i = 0; i < 4; i++) acc[f][i] = 0.0f;
}

// ---- staging: 16B cp.async, XOR-swizzled dst ----
__device__ __forceinline__ void stage128(u32 dst, const __half* src, int rows, int tid) {
    for (int i = tid; i < rows * 16; i += 256) {
        int r = i >> 4, c = i & 15;
        cpa16(dst + (u32)r * 256u + (u32)((c ^ (r & 7)) << 4), src + (size_t)r * 128 + c * 8);
    }
}
__device__ __forceinline__ void stage32s(u32 dst, const __half* src, int tid) {
    for (int i = tid; i < 128 * 4; i += 256) {
        int r = i >> 2, c = i & 3;
        cpa16(dst + (u32)r * 64u + (u32)((c ^ (r & 3)) << 4), src + (size_t)r * 32 + c * 8);
    }
}

// ===================== prep: transpose + hi/lo split all weights =====================
__global__ void k_prep(const float* __restrict__ anc_wi, const float* __restrict__ anc_wh,
                       const float* __restrict__ frat_wi, const float* __restrict__ frat_wh,
                       const float* __restrict__ uf_w, const float* __restrict__ ua_w,
                       const float* __restrict__ h2o_w)
{
    int t = blockIdx.x * blockDim.x + threadIdx.x, NT = gridDim.x * blockDim.x;
    for (int i = t; i < 3 * 16384; i += NT) {
        int g = i >> 14, rem = i & 16383, k = rem >> 7, n = rem & 127;
        int d = g * 32768 + n * 128 + k;
        __half h, l;
        wsplit(anc_wh[i], h, l);  g_wt[W_ANC_WH + d] = h;  g_wt[W_ANC_WH + d + 16384] = l;
        wsplit(frat_wh[i], h, l); g_wt[W_FRAT_WH + d] = h; g_wt[W_FRAT_WH + d + 16384] = l;
    }
    for (int i = t; i < 3 * 4096; i += NT) {
        int g = i >> 12, rem = i & 4095, k = rem >> 7, n = rem & 127;
        int d = g * 8192 + n * 32 + k;
        __half h, l;
        wsplit(anc_wi[i], h, l);  g_wt[W_ANC_WI + d] = h;  g_wt[W_ANC_WI + d + 4096] = l;
        wsplit(frat_wi[i], h, l); g_wt[W_FRAT_WI + d] = h; g_wt[W_FRAT_WI + d + 4096] = l;
    }
    for (int i = t; i < 16384; i += NT) {
        int k = i >> 7, n = i & 127, d = n * 128 + k;
        __half h, l;
        wsplit(uf_w[i], h, l); g_wt[W_UF + d] = h; g_wt[W_UF + d + 16384] = l;
        wsplit(ua_w[i], h, l); g_wt[W_UA + d] = h; g_wt[W_UA + d + 16384] = l;
    }
    for (int i = t; i < 4096; i += NT) {
        int k = i >> 5, n = i & 31, d = n * 128 + k;
        __half h, l;
        wsplit(h2o_w[i], h, l); g_wt[W_H2O + d] = h; g_wt[W_H2O + d + 4096] = l;
    }
}

// ===================== init =====================
__global__ __launch_bounds__(128, 4)
void init_k(const float* __restrict__ z, const float* __restrict__ w,
            const float* __restrict__ b, __half* __restrict__ oh, __half* __restrict__ ol)
{
    const int g = threadIdx.x;
    const int row0 = blockIdx.x * 16;
    __shared__ float s[16][HD];
    for (int r = 0; r < 16; r++) s[r][g] = z[(size_t)(row0 + r) * HD + g];
    __syncthreads();
    float a[16];
#pragma unroll
    for (int r = 0; r < 16; r++) a[r] = 0.0f;
    for (int j = 0; j < HD; j++) {
        float wv = __ldg(w + (size_t)j * HD + g);
#pragma unroll
        for (int r = 0; r < 16; r++) a[r] += s[r][j] * wv;
    }
    float bg = __ldg(b + g);
#pragma unroll
    for (int r = 0; r < 16; r++) {
        __half h, l; wsplit(a[r] + bg, h, l);
        size_t o = (size_t)(row0 + r) * HD + g;
        oh[o] = h; ol[o] = l;
    }
}

// ===================== GRU fused (tensor, double-buffered B, r/z/n in regs) =====================
#define oAH  0
#define oAXH 32768
#define oWI  40960
#define oWH  90112
#define oBIA 221184
#define GRU_DS 223232

__global__ __launch_bounds__(256)
void gru_k(const __half* __restrict__ xh, const __half* __restrict__ xl,
           const __half* __restrict__ hh, const __half* __restrict__ hl,
           const __half* __restrict__ whT, const __half* __restrict__ wiT,
           const float* __restrict__ bi, const float* __restrict__ bhp,
           __half* __restrict__ oh, __half* __restrict__ ol)
{
    extern __shared__ char dsm[];
    const u32 S = smaddr(dsm);
    const int tid = threadIdx.x, lane = tid & 31, wid = tid >> 5;
    const int row0 = blockIdx.x * 128;
    const int m0 = (wid & 3) * 32, n0 = (wid >> 2) * 64;

    if (tid < 128) {
        float4 bv = make_float4(__ldg(bi + tid) + __ldg(bhp + tid),
                                __ldg(bi + 128 + tid) + __ldg(bhp + 128 + tid),
                                __ldg(bhp + 256 + tid), __ldg(bi + 256 + tid));
        *(float4*)(dsm + oBIA + tid * 16) = bv;
    }
    stage128(S + oAH, hh + (size_t)row0 * 128, 128, tid);
    stage32s(S + oAXH, xh + (size_t)row0 * 32, tid);
#pragma unroll
    for (int p = 0; p < 6; p++)
        stage32s(S + oWI + p * 8192, wiT + p * 4096, tid);
    stage128(S + oWH, whT, 128, tid);                    // gate r hi -> buf0
    stage128(S + oWH + 32768, whT + 16384, 128, tid);    // gate r lo
    cpcommit(); cpwait0(); __syncthreads();

    // prefetch gate n (g2) weights into buf1
    stage128(S + oWH + 65536, whT + 65536, 128, tid);
    stage128(S + oWH + 98304, whT + 81920, 128, tid);
    cpcommit();

    const int lr = lane >> 2, lc = 2 * (lane & 3);
    const __half* hlr = hl + (size_t)row0 * 128;
    const __half* xlr = xl + (size_t)row0 * 32;
    float acc[16][4];
    u32 rq[32], nq[32];

    // ---- gate r (buf0, wi slab 0) ----
    zacc(acc);
    for (int kc = 0; kc < 8; kc++)
        kstep128v2(acc, S + oAH, hlr, S + oWH, S + oWH + 32768, m0, n0, lane, kc);
    for (int kc = 0; kc < 2; kc++)
        kstep32v2(acc, S + oAXH, xlr, S + oWI, S + oWI + 8192, m0, n0, lane, kc);
#pragma unroll
    for (int f = 0; f < 16; f++) {
        int colb = n0 + (f & 7) * 8 + lc;
        float b0 = ((const float*)(dsm + oBIA + colb * 16))[0];
        float b1 = ((const float*)(dsm + oBIA + (colb + 1) * 16))[0];
        rq[2 * f]     = (u32)(fsig(acc[f][0] + b0) * 65535.f + 0.5f)
                      | ((u32)(fsig(acc[f][1] + b1) * 65535.f + 0.5f) << 16);
        rq[2 * f + 1] = (u32)(fsig(acc[f][2] + b0) * 65535.f + 0.5f)
                      | ((u32)(fsig(acc[f][3] + b1) * 65535.f + 0.5f) << 16);
    }
    cpwait0(); __syncthreads();
    // prefetch gate z (g1) into buf0 (all warps done reading it)
    stage128(S + oWH, whT + 32768, 128, tid);
    stage128(S + oWH + 32768, whT + 49152, 128, tid);
    cpcommit();

    // ---- gate n (buf1, wi slab 2): gh2 then fold r, then gi2 accumulates ----
    zacc(acc);
    for (int kc = 0; kc < 8; kc++)
        kstep128v2(acc, S + oAH, hlr, S + oWH + 65536, S + oWH + 98304, m0, n0, lane, kc);
    const float QU = 1.0f / 65535.0f;
#pragma unroll
    for (int f = 0; f < 16; f++) {
        int colb = n0 + (f & 7) * 8 + lc;
        const float* bp = (const float*)(dsm + oBIA + colb * 16);
        const float* bq = (const float*)(dsm + oBIA + (colb + 1) * 16);
#pragma unroll
        for (int hp = 0; hp < 2; hp++) {
            u32 rv = rq[2 * f + hp];
            acc[f][hp * 2]     = (float)(rv & 0xffffu) * QU * (acc[f][hp * 2]     + bp[2]) + bp[3];
            acc[f][hp * 2 + 1] = (float)(rv >> 16)     * QU * (acc[f][hp * 2 + 1] + bq[2]) + bq[3];
        }
    }
    for (int kc = 0; kc < 2; kc++)
        kstep32v2(acc, S + oAXH, xlr, S + oWI + 32768, S + oWI + 40960, m0, n0, lane, kc);
#pragma unroll
    for (int f = 0; f < 16; f++) {
#pragma unroll
        for (int hp = 0; hp < 2; hp++) {
            float nn0 = ftanh(acc[f][hp * 2]), nn1 = ftanh(acc[f][hp * 2 + 1]);
            nq[2 * f + hp] = (u32)((nn0 * 0.5f + 0.5f) * 65535.f + 0.5f)
                           | ((u32)((nn1 * 0.5f + 0.5f) * 65535.f + 0.5f) << 16);
        }
    }
    cpwait0(); __syncthreads();

    // ---- gate z (buf0, wi slab 1) + blend + store ----
    zacc(acc);
    for (int kc = 0; kc < 8; kc++)
        kstep128v2(acc, S + oAH, hlr, S + oWH, S + oWH + 32768, m0, n0, lane, kc);
    for (int kc = 0; kc < 2; kc++)
        kstep32v2(acc, S + oAXH, xlr, S + oWI + 16384, S + oWI + 24576, m0, n0, lane, kc);

    const float QN = 2.0f / 65535.0f;
#pragma unroll
    for (int f = 0; f < 16; f++) {
        int colb = n0 + (f & 7) * 8 + lc;
        float b0 = ((const float*)(dsm + oBIA + colb * 16))[1];
        float b1 = ((const float*)(dsm + oBIA + (colb + 1) * 16))[1];
#pragma unroll
        for (int hp = 0; hp < 2; hp++) {
            int row = m0 + (f >> 3) * 16 + lr + hp * 8;
            float zz0 = fsig(acc[f][hp * 2] + b0), zz1 = fsig(acc[f][hp * 2 + 1] + b1);
            u32 nv = nq[2 * f + hp];
            float nn0 = (float)(nv & 0xffffu) * QN - 1.0f;
            float nn1 = (float)(nv >> 16) * QN - 1.0f;
            size_t go = (size_t)(row0 + row) * 128 + colb;
            __half2 h2h = *(const __half2*)(hh + go), h2l = *(const __half2*)(hl + go);
            float h0 = __half2float(__low2half(h2h)) + __half2float(__low2half(h2l));
            float h1 = __half2float(__high2half(h2h)) + __half2float(__high2half(h2l));
            float o0 = (1.0f - zz0) * nn0 + zz0 * h0;
            float o1 = (1.0f - zz1) * nn1 + zz1 * h1;
            __half H0, L0, H1, L1;
            wsplit(o0, H0, L0); wsplit(o1, H1, L1);
            *(__half2*)(oh + go) = __halves2half2(H0, H1);
            *(__half2*)(ol + go) = __halves2half2(L0, L1);
        }
    }
}

// ===================== comb (tensor, double-buffered B) =====================
#define cFH  0
#define cAH2 32768
#define cB   65536
#define COMB_DS 196608

__global__ __launch_bounds__(256)
void comb_k(const __half* __restrict__ fh, const __half* __restrict__ fl,
            const __half* __restrict__ ah, const __half* __restrict__ al,
            const __half* __restrict__ ufT, const __half* __restrict__ uaT,
            const float* __restrict__ ufb, const float* __restrict__ uab,
            __half* __restrict__ oh, __half* __restrict__ ol)
{
    extern __shared__ char dsm[];
    const u32 S = smaddr(dsm);
    const int tid = threadIdx.x, lane = tid & 31, wid = tid >> 5;
    const int row0 = blockIdx.x * 128;
    const int m0 = (wid & 3) * 32, n0 = (wid >> 2) * 64;

    stage128(S + cFH, fh + (size_t)row0 * 128, 128, tid);
    stage128(S + cAH2, ah + (size_t)row0 * 128, 128, tid);
    stage128(S + cB, ufT, 128, tid);
    stage128(S + cB + 32768, ufT + 16384, 128, tid);
    cpcommit(); cpwait0(); __syncthreads();
    stage128(S + cB + 65536, uaT, 128, tid);
    stage128(S + cB + 98304, uaT + 16384, 128, tid);
    cpcommit();

    const __half* flr = fl + (size_t)row0 * 128;
    const __half* alr = al + (size_t)row0 * 128;
    float acc[16][4];
    zacc(acc);
    for (int kc = 0; kc < 8; kc++)
        kstep128v2(acc, S + cFH, flr, S + cB, S + cB + 32768, m0, n0, lane, kc);
    cpwait0(); __syncthreads();
    for (int kc = 0; kc < 8; kc++)
        kstep128v2(acc, S + cAH2, alr, S + cB + 65536, S + cB + 98304, m0, n0, lane, kc);

    const int lr = lane >> 2, lc = 2 * (lane & 3);
#pragma unroll
    for (int f = 0; f < 16; f++) {
        int colb = n0 + (f & 7) * 8 + lc;
        float b0 = __ldg(ufb + colb) + __ldg(uab + colb);
        float b1 = __ldg(ufb + colb + 1) + __ldg(uab + colb + 1);
#pragma unroll
        for (int hp = 0; hp < 2; hp++) {
            int row = m0 + (f >> 3) * 16 + lr + hp * 8;
            float o0 = ftanh(acc[f][hp * 2] + b0);
            float o1 = ftanh(acc[f][hp * 2 + 1] + b1);
            __half H0, L0, H1, L1;
            wsplit(o0, H0, L0); wsplit(o1, H1, L1);
            size_t go = (size_t)(row0 + row) * 128 + colb;
            *(__half2*)(oh + go) = __halves2half2(H0, H1);
            *(__half2*)(ol + go) = __halves2half2(L0, L1);
        }
    }
}

// ===================== node (tensor + fused softmax) =====================
#define nAH 0
#define nBH 32768
#define nBL 40960
#define nPR 49152
#define NODE_DS 65536

__global__ __launch_bounds__(256)
void node_k(const __half* __restrict__ hh, const __half* __restrict__ hl,
            const __half* __restrict__ h2oT, const float* __restrict__ b,
            float* __restrict__ pred, __half* __restrict__ ph, __half* __restrict__ pl)
{
    extern __shared__ char dsm[];
    const u32 S = smaddr(dsm);
    const int tid = threadIdx.x, lane = tid & 31, wid = tid >> 5;
    const int row0 = blockIdx.x * 128;
    const int m0 = wid * 16;

    stage128(S + nAH, hh + (size_t)row0 * 128, 128, tid);
    stage128(S + nBH, h2oT, 32, tid);
    stage128(S + nBL, h2oT + 4096, 32, tid);
    cpcommit(); cpwait0(); __syncthreads();

    const __half* hlr = hl + (size_t)row0 * 128;
    float acc[4][4];
#pragma unroll
    for (int f = 0; f < 4; f++)
#pragma unroll
        for (int i = 0; i < 4; i++) acc[f][i] = 0.0f;

    for (int kc = 0; kc < 8; kc++) {
        u32 ahr[4], alr[4];
        ldmA128(ahr, S + nAH, m0, lane, kc);
        ldgA(alr, hlr, 128, m0, lane, kc);
#pragma unroll
        for (int G = 0; G < 2; G++) {
            u32 bh[4], bl[4];
            ldmB128(bh, S + nBH, G * 16, lane, kc);
            ldmB128(bl, S + nBL, G * 16, lane, kc);
            mmaf(acc[G * 2], ahr, bh);     mmaf(acc[G * 2 + 1], ahr, bh + 2);
            mmaf(acc[G * 2], ahr, bl);     mmaf(acc[G * 2 + 1], ahr, bl + 2);
            mmaf(acc[G * 2], alr, bh);     mmaf(acc[G * 2 + 1], alr, bh + 2);
        }
    }
    const int lr = lane >> 2, lc = 2 * (lane & 3);
#pragma unroll
    for (int f = 0; f < 4; f++) {
#pragma unroll
        for (int i = 0; i < 4; i++) {
            int row = m0 + lr + (i >> 1) * 8;
            int col = f * 8 + lc + (i & 1);
            *(float*)(dsm + nPR + (row * 32 + col) * 4) = acc[f][i] + __ldg(b + col);
        }
    }
    __syncthreads();
    if (tid < 128) {
        int row = tid;
        const float* pr = (const float*)(dsm + nPR + row * 128);
        float v[32], mx = -1e30f;
#pragma unroll
        for (int i = 0; i < 32; i++) { v[i] = pr[i]; mx = fmaxf(mx, v[i]); }
        float e[32], sum = 0.0f;
#pragma unroll
        for (int i = 0; i < 32; i++) { e[i] = __expf(v[i] - mx); sum += e[i]; }
        float inv = __fdividef(1.0f, sum);
        size_t go = (size_t)(row0 + row) * 32;
        float4* pg = (float4*)(pred + go);
#pragma unroll
        for (int q = 0; q < 8; q++)
            pg[q] = make_float4(v[4 * q], v[4 * q + 1], v[4 * q + 2], v[4 * q + 3]);
#pragma unroll
        for (int j = 0; j < 16; j++) {
            float p0 = e[2 * j] * inv, p1 = e[2 * j + 1] * inv;
            __half H0, L0, H1, L1;
            wsplit(p0, H0, L0); wsplit(p1, H1, L1);
            *(__half2*)(ph + go + 2 * j) = __halves2half2(H0, H1);
            *(__half2*)(pl + go + 2 * j) = __halves2half2(L0, L1);
        }
    }
}

// ===================== host =====================
namespace {
struct LCtx {
    const __half* wt;
    const float *h2o_b;
    const float *anc_bi, *anc_bh, *frat_bi, *frat_bh;
    const float *ua_b, *uf_b;
    __half *hAh, *hAl, *hFh, *hFl, *prh, *prl;
    float* out;
    int idx;
};

void rec(LCtx& c, int L, int d)
{
    size_t hL = (size_t)L * BATCH * HD, hL1 = (size_t)(L + 1) * BATCH * HD;
    size_t pL = (size_t)L * BATCH * OD, pL1 = (size_t)(L + 1) * BATCH * OD;

    node_k<<<BATCH / 128, 256, NODE_DS>>>(c.hAh + hL, c.hAl + hL,
                                          c.wt + W_H2O, c.h2o_b,
                                          c.out + (size_t)c.idx * BATCH * OD,
                                          c.prh + pL, c.prl + pL);
    c.idx++;
    if (d == 0) return;

    gru_k<<<BATCH / 128, 256, GRU_DS>>>(c.prh + pL, c.prl + pL,
                                        c.hAh + hL, c.hAl + hL,
                                        c.wt + W_ANC_WH, c.wt + W_ANC_WI,
                                        c.anc_bi, c.anc_bh,
                                        c.hAh + hL1, c.hAl + hL1);
    rec(c, L + 1, d - 1);

    size_t fL = (size_t)L * BATCH * HD;
    gru_k<<<BATCH / 128, 256, GRU_DS>>>(c.prh + pL1, c.prl + pL1,
                                        c.hAh + hL1, c.hAl + hL1,
                                        c.wt + W_FRAT_WH, c.wt + W_FRAT_WI,
                                        c.frat_bi, c.frat_bh,
                                        c.hFh + fL, c.hFl + fL);

    comb_k<<<BATCH / 128, 256, COMB_DS>>>(c.hFh + fL, c.hFl + fL,
                                          c.hAh + hL, c.hAl + hL,
                                          c.wt + W_UF, c.wt + W_UA,
                                          c.uf_b, c.ua_b,
                                          c.hAh + hL1, c.hAl + hL1);
    rec(c, L + 1, d - 1);
}
} // namespace

extern "C" void kernel_launch(void* const* d_in, const int* in_sizes, int n_in,
                              void* d_out, int out_size)
{
    const float* z       = (const float*)d_in[0];
    const float* z2h_w   = (const float*)d_in[1];
    const float* z2h_b   = (const float*)d_in[2];
    const float* h2o_w   = (const float*)d_in[3];
    const float* h2o_b   = (const float*)d_in[4];
    const float* anc_wi  = (const float*)d_in[5];
    const float* anc_wh  = (const float*)d_in[6];
    const float* anc_bi  = (const float*)d_in[7];
    const float* anc_bh  = (const float*)d_in[8];
    const float* frat_wi = (const float*)d_in[9];
    const float* frat_wh = (const float*)d_in[10];
    const float* frat_bi = (const float*)d_in[11];
    const float* frat_bh = (const float*)d_in[12];
    const float* ua_w    = (const float*)d_in[13];
    const float* ua_b    = (const float*)d_in[14];
    const float* uf_w    = (const float*)d_in[15];
    const float* uf_b    = (const float*)d_in[16];

    cudaFuncSetAttribute(gru_k,  cudaFuncAttributeMaxDynamicSharedMemorySize, GRU_DS);
    cudaFuncSetAttribute(comb_k, cudaFuncAttributeMaxDynamicSharedMemorySize, COMB_DS);
    cudaFuncSetAttribute(node_k, cudaFuncAttributeMaxDynamicSharedMemorySize, NODE_DS);

    __half *wt, *hAh, *hAl, *hFh, *hFl, *prh, *prl;
    cudaGetSymbolAddress((void**)&wt, g_wt);
    cudaGetSymbolAddress((void**)&hAh, g_hAh);
    cudaGetSymbolAddress((void**)&hAl, g_hAl);
    cudaGetSymbolAddress((void**)&hFh, g_hFh);
    cudaGetSymbolAddress((void**)&hFl, g_hFl);
    cudaGetSymbolAddress((void**)&prh, g_prh);
    cudaGetSymbolAddress((void**)&prl, g_prl);

    k_prep<<<128, 256>>>(anc_wi, anc_wh, frat_wi, frat_wh, uf_w, ua_w, h2o_w);
    init_k<<<BATCH / 16, 128>>>(z, z2h_w, z2h_b, hAh, hAl);

    LCtx c;
    c.wt = wt; c.h2o_b = h2o_b;
    c.anc_bi = anc_bi; c.anc_bh = anc_bh;
    c.frat_bi = frat_bi; c.frat_bh = frat_bh;
    c.ua_b = ua_b; c.uf_b = uf_b;
    c.hAh = hAh; c.hAl = hAl; c.hFh = hFh; c.hFl = hFl;
    c.prh = prh; c.prl = prl;
    c.out = (float*)d_out;
    c.idx = 0;
    rec(c, 0, DEPTH);
}

// round 7
// speedup vs baseline: 1.1270x; 1.1270x over previous
#include <cuda_runtime.h>
#include <cuda_fp16.h>
#include <cstdint>

#define BATCH 32768
#define HD 128
#define OD 32
#define DEPTH 5
typedef uint32_t u32;

// ---- weight tile offsets in g_wt (halves) ----
#define W_ANC_WH  0
#define W_FRAT_WH 98304
#define W_ANC_WI  196608
#define W_FRAT_WI 221184
#define W_UF      245760
#define W_UA      278528
#define W_H2O     311296
__device__ __half g_wt[319488];

__device__ __half g_hAh[DEPTH + 1][BATCH * HD];
__device__ __half g_hAl[DEPTH + 1][BATCH * HD];
__device__ __half g_prh[DEPTH + 1][BATCH * OD];
__device__ __half g_prl[DEPTH + 1][BATCH * OD];

// ===================== helpers (R5-proven) =====================
__device__ __forceinline__ u32 smaddr(const void* p) {
    u32 a;
    asm("{ .reg .u64 t; cvta.to.shared.u64 t, %1; cvt.u32.u64 %0, t; }" : "=r"(a) : "l"(p));
    return a;
}
__device__ __forceinline__ void cpa16(u32 d, const void* s) {
    asm volatile("cp.async.cg.shared.global [%0], [%1], 16;" :: "r"(d), "l"(s) : "memory");
}
__device__ __forceinline__ void cpcommit() {
    asm volatile("cp.async.commit_group;" ::: "memory");
}
__device__ __forceinline__ void cpwait0() {
    asm volatile("cp.async.wait_group 0;" ::: "memory");
}
__device__ __forceinline__ void ldm4(u32* r, u32 a) {
    asm volatile("ldmatrix.sync.aligned.m8n8.x4.shared.b16 {%0,%1,%2,%3}, [%4];"
                 : "=r"(r[0]), "=r"(r[1]), "=r"(r[2]), "=r"(r[3]) : "r"(a));
}
__device__ __forceinline__ void mmaf(float* c, const u32* a, const u32* b) {
    asm volatile(
        "mma.sync.aligned.m16n8k16.row.col.f32.f16.f16.f32 "
        "{%0,%1,%2,%3},{%4,%5,%6,%7},{%8,%9},{%0,%1,%2,%3};"
        : "+f"(c[0]), "+f"(c[1]), "+f"(c[2]), "+f"(c[3])
        : "r"(a[0]), "r"(a[1]), "r"(a[2]), "r"(a[3]), "r"(b[0]), "r"(b[1]));
}
__device__ __forceinline__ float fsig(float x)  { return __fdividef(1.0f, 1.0f + __expf(-x)); }
__device__ __forceinline__ float ftanh(float x) { float u = __expf(2.0f * x); return 1.0f - __fdividef(2.0f, u + 1.0f); }
__device__ __forceinline__ void wsplit(float v, __half& h, __half& l) {
    h = __float2half_rn(v);
    l = __float2half_rn(v - __half2float(h));
}

__device__ __forceinline__ void ldmA128(u32* r, u32 base, int m0, int lane, int kc) {
    int row = m0 + (lane & 15), c16 = 2 * kc + (lane >> 4);
    ldm4(r, base + (u32)row * 256u + (u32)((c16 ^ (row & 7)) << 4));
}
__device__ __forceinline__ void ldmB128(u32* r, u32 base, int n0, int lane, int kc) {
    int row = n0 + (lane & 7) + ((lane >> 4) << 3), c16 = 2 * kc + ((lane >> 3) & 1);
    ldm4(r, base + (u32)row * 256u + (u32)((c16 ^ (row & 7)) << 4));
}
__device__ __forceinline__ void ldmA32(u32* r, u32 base, int m0, int lane, int kc) {
    int row = m0 + (lane & 15), c4 = 2 * kc + (lane >> 4);
    ldm4(r, base + (u32)row * 64u + (u32)((c4 ^ (row & 3)) << 4));
}
__device__ __forceinline__ void ldmB32(u32* r, u32 base, int n0, int lane, int kc) {
    int row = n0 + (lane & 7) + ((lane >> 4) << 3), c4 = 2 * kc + ((lane >> 3) & 1);
    ldm4(r, base + (u32)row * 64u + (u32)((c4 ^ (row & 3)) << 4));
}

// ---- 32x64 warp tile, 3-term hi/lo, one k16 chunk (R5 core) ----
__device__ __forceinline__ void kstep128(float (*acc)[4], u32 AH, u32 AL, u32 BH, u32 BL,
                                         int m0, int n0, int lane, int kc) {
    u32 a[4][4];
    ldmA128(a[0], AH, m0, lane, kc);      ldmA128(a[1], AH, m0 + 16, lane, kc);
    ldmA128(a[2], AL, m0, lane, kc);      ldmA128(a[3], AL, m0 + 16, lane, kc);
#pragma unroll
    for (int G = 0; G < 4; G++) {
        u32 bh[4], bl[4];
        ldmB128(bh, BH, n0 + G * 16, lane, kc);
        ldmB128(bl, BL, n0 + G * 16, lane, kc);
#pragma unroll
        for (int mf = 0; mf < 2; mf++) {
            float* c0 = acc[mf * 8 + G * 2];
            float* c1 = acc[mf * 8 + G * 2 + 1];
            mmaf(c0, a[mf], bh);     mmaf(c1, a[mf], bh + 2);
            mmaf(c0, a[mf], bl);     mmaf(c1, a[mf], bl + 2);
            mmaf(c0, a[2 + mf], bh); mmaf(c1, a[2 + mf], bh + 2);
        }
    }
}
__device__ __forceinline__ void kstep32(float (*acc)[4], u32 AH, u32 AL, u32 BH, u32 BL,
                                        int m0, int n0, int lane, int kc) {
    u32 a[4][4];
    ldmA32(a[0], AH, m0, lane, kc);      ldmA32(a[1], AH, m0 + 16, lane, kc);
    ldmA32(a[2], AL, m0, lane, kc);      ldmA32(a[3], AL, m0 + 16, lane, kc);
#pragma unroll
    for (int G = 0; G < 4; G++) {
        u32 bh[4], bl[4];
        ldmB32(bh, BH, n0 + G * 16, lane, kc);
        ldmB32(bl, BL, n0 + G * 16, lane, kc);
#pragma unroll
        for (int mf = 0; mf < 2; mf++) {
            float* c0 = acc[mf * 8 + G * 2];
            float* c1 = acc[mf * 8 + G * 2 + 1];
            mmaf(c0, a[mf], bh);     mmaf(c1, a[mf], bh + 2);
            mmaf(c0, a[mf], bl);     mmaf(c1, a[mf], bl + 2);
            mmaf(c0, a[2 + mf], bh); mmaf(c1, a[2 + mf], bh + 2);
        }
    }
}
__device__ __forceinline__ void zacc(float (*acc)[4]) {
#pragma unroll
    for (int f = 0; f < 16; f++)
#pragma unroll
        for (int i = 0; i < 4; i++) acc[f][i] = 0.0f;
}

__device__ __forceinline__ void stage128(u32 dst, const __half* src, int rows, int tid) {
    for (int i = tid; i < rows * 16; i += 256) {
        int r = i >> 4, c = i & 15;
        cpa16(dst + (u32)r * 256u + (u32)((c ^ (r & 7)) << 4), src + (size_t)r * 128 + c * 8);
    }
}
__device__ __forceinline__ void stage32s(u32 dst, const __half* src, int tid) {
    for (int i = tid; i < 128 * 4; i += 256) {
        int r = i >> 2, c = i & 3;
        cpa16(dst + (u32)r * 64u + (u32)((c ^ (r & 3)) << 4), src + (size_t)r * 32 + c * 8);
    }
}

// ===================== prep =====================
__global__ void k_prep(const float* __restrict__ anc_wi, const float* __restrict__ anc_wh,
                       const float* __restrict__ frat_wi, const float* __restrict__ frat_wh,
                       const float* __restrict__ uf_w, const float* __restrict__ ua_w,
                       const float* __restrict__ h2o_w)
{
    int t = blockIdx.x * blockDim.x + threadIdx.x, NT = gridDim.x * blockDim.x;
    for (int i = t; i < 3 * 16384; i += NT) {
        int g = i >> 14, rem = i & 16383, k = rem >> 7, n = rem & 127;
        int d = g * 32768 + n * 128 + k;
        __half h, l;
        wsplit(anc_wh[i], h, l);  g_wt[W_ANC_WH + d] = h;  g_wt[W_ANC_WH + d + 16384] = l;
        wsplit(frat_wh[i], h, l); g_wt[W_FRAT_WH + d] = h; g_wt[W_FRAT_WH + d + 16384] = l;
    }
    for (int i = t; i < 3 * 4096; i += NT) {
        int g = i >> 12, rem = i & 4095, k = rem >> 7, n = rem & 127;
        int d = g * 8192 + n * 32 + k;
        __half h, l;
        wsplit(anc_wi[i], h, l);  g_wt[W_ANC_WI + d] = h;  g_wt[W_ANC_WI + d + 4096] = l;
        wsplit(frat_wi[i], h, l); g_wt[W_FRAT_WI + d] = h; g_wt[W_FRAT_WI + d + 4096] = l;
    }
    for (int i = t; i < 16384; i += NT) {
        int k = i >> 7, n = i & 127, d = n * 128 + k;
        __half h, l;
        wsplit(uf_w[i], h, l); g_wt[W_UF + d] = h; g_wt[W_UF + d + 16384] = l;
        wsplit(ua_w[i], h, l); g_wt[W_UA + d] = h; g_wt[W_UA + d + 16384] = l;
    }
    for (int i = t; i < 4096; i += NT) {
        int k = i >> 5, n = i & 31, d = n * 128 + k;
        __half h, l;
        wsplit(h2o_w[i], h, l); g_wt[W_H2O + d] = h; g_wt[W_H2O + d + 4096] = l;
    }
}

// ===================== init =====================
__global__ __launch_bounds__(128, 4)
void init_k(const float* __restrict__ z, const float* __restrict__ w,
            const float* __restrict__ b, __half* __restrict__ oh, __half* __restrict__ ol)
{
    const int g = threadIdx.x;
    const int row0 = blockIdx.x * 16;
    __shared__ float s[16][HD];
    for (int r = 0; r < 16; r++) s[r][g] = z[(size_t)(row0 + r) * HD + g];
    __syncthreads();
    float a[16];
#pragma unroll
    for (int r = 0; r < 16; r++) a[r] = 0.0f;
    for (int j = 0; j < HD; j++) {
        float wv = __ldg(w + (size_t)j * HD + g);
#pragma unroll
        for (int r = 0; r < 16; r++) a[r] += s[r][j] * wv;
    }
    float bg = __ldg(b + g);
#pragma unroll
    for (int r = 0; r < 16; r++) {
        __half h, l; wsplit(a[r] + bg, h, l);
        size_t o = (size_t)(row0 + r) * HD + g;
        oh[o] = h; ol[o] = l;
    }
}

// ===================== shared SMEM layout for fused kernels =====================
#define oAH  0
#define oAL  32768
#define oAXH 65536
#define oAXL 73728
#define oBH  81920
#define oBL  114688
#define oBXH 147456
#define oBXL 155648
#define oRS  163840
#define oZS  196608
#define oBIA 229376
#define FUSE_DS 231424

// ---- shared GRU gate machinery (R5 body) ----
// computes gates r,z into RS/ZS buffers, then gate n; leaves final o-values in acc.
// Assumes A panels (oAH/oAL), x panels (oAXH/oAXL), bias (oBIA) ready and gate-r B staged+committed but NOT waited.
__device__ __forceinline__ void gru_gates(char* dsm, u32 S, const __half* whT, const __half* wiT,
                                          int tid, int lane, int wid, int m0, int n0,
                                          float (*acc)[4])
{
    const int lr = lane >> 2, lc = 2 * (lane & 3);
    cpwait0(); __syncthreads();

#pragma unroll 1
    for (int gate = 0; gate < 2; gate++) {
        zacc(acc);
        for (int kc = 0; kc < 8; kc++)
            kstep128(acc, S + oAH, S + oAL, S + oBH, S + oBL, m0, n0, lane, kc);
        for (int kc = 0; kc < 2; kc++)
            kstep32(acc, S + oAXH, S + oAXL, S + oBXH, S + oBXL, m0, n0, lane, kc);
        int oRZ = gate ? oZS : oRS;
#pragma unroll
        for (int f = 0; f < 16; f++) {
            int mf = f >> 3, ng = f & 7;
            int colb = n0 + ng * 8 + lc;
            float b0 = ((const float*)(dsm + oBIA + colb * 16))[gate];
            float b1 = ((const float*)(dsm + oBIA + (colb + 1) * 16))[gate];
#pragma unroll
            for (int hp = 0; hp < 2; hp++) {
                int row = m0 + mf * 16 + lr + hp * 8;
                float v0 = fsig(acc[f][hp * 2] + b0);
                float v1 = fsig(acc[f][hp * 2 + 1] + b1);
                ushort2 u = make_ushort2((unsigned short)(v0 * 65535.f + 0.5f),
                                         (unsigned short)(v1 * 65535.f + 0.5f));
                *(ushort2*)(dsm + oRZ + row * 256 + colb * 2) = u;
            }
        }
        __syncthreads();
        const __half* wh2 = whT + (size_t)(gate + 1) * 32768;
        const __half* wi2 = wiT + (size_t)(gate + 1) * 8192;
        stage128(S + oBH, wh2, 128, tid);
        stage128(S + oBL, wh2 + 16384, 128, tid);
        stage32s(S + oBXH, wi2, tid);
        stage32s(S + oBXL, wi2 + 4096, tid);
        cpcommit(); cpwait0(); __syncthreads();
    }

    // gate n
    zacc(acc);
    for (int kc = 0; kc < 8; kc++)
        kstep128(acc, S + oAH, S + oAL, S + oBH, S + oBL, m0, n0, lane, kc);
    float acc2[16][4];
    zacc(acc2);
    for (int kc = 0; kc < 2; kc++)
        kstep32(acc2, S + oAXH, S + oAXL, S + oBXH, S + oBXL, m0, n0, lane, kc);

    // epilogue: final hidden values into acc
    const float Q = 1.0f / 65535.0f;
#pragma unroll
    for (int f = 0; f < 16; f++) {
        int mf = f >> 3, ng = f & 7;
        int colb = n0 + ng * 8 + lc;
        const float* bp = (const float*)(dsm + oBIA + colb * 16);
        const float* bq = (const float*)(dsm + oBIA + (colb + 1) * 16);
#pragma unroll
        for (int hp = 0; hp < 2; hp++) {
            int row = m0 + mf * 16 + lr + hp * 8;
            ushort2 r2 = *(ushort2*)(dsm + oRS + row * 256 + colb * 2);
            ushort2 z2 = *(ushort2*)(dsm + oZS + row * 256 + colb * 2);
            u32 aoff = (u32)row * 256u + (u32)((((colb >> 3) ^ (row & 7)) << 4)) + (colb & 7) * 2;
            __half2 hhv = *(__half2*)(dsm + oAH + aoff);
            __half2 hlv = *(__half2*)(dsm + oAL + aoff);
            float rr0 = r2.x * Q, rr1 = r2.y * Q;
            float zz0 = z2.x * Q, zz1 = z2.y * Q;
            float nn0 = ftanh(acc2[f][hp * 2]     + bp[3] + rr0 * (acc[f][hp * 2]     + bp[2]));
            float nn1 = ftanh(acc2[f][hp * 2 + 1] + bq[3] + rr1 * (acc[f][hp * 2 + 1] + bq[2]));
            float h0 = __half2float(__low2half(hhv)) + __half2float(__low2half(hlv));
            float h1 = __half2float(__high2half(hhv)) + __half2float(__high2half(hlv));
            acc[f][hp * 2]     = (1.0f - zz0) * nn0 + zz0 * h0;
            acc[f][hp * 2 + 1] = (1.0f - zz1) * nn1 + zz1 * h1;
        }
    }
}

__device__ __forceinline__ void load_bias(char* dsm, const float* bi, const float* bhp, int tid) {
    if (tid < 128) {
        float4 bv = make_float4(__ldg(bi + tid) + __ldg(bhp + tid),
                                __ldg(bi + 128 + tid) + __ldg(bhp + 128 + tid),
                                __ldg(bhp + 256 + tid), __ldg(bi + 256 + tid));
        *(float4*)(dsm + oBIA + tid * 16) = bv;
    }
}

// ===================== nodegru: node(pred+softmax) + anc GRU =====================
__global__ __launch_bounds__(256)
void nodegru_k(const __half* __restrict__ hh, const __half* __restrict__ hl,
               const __half* __restrict__ h2oT, const float* __restrict__ h2ob,
               float* __restrict__ pred, __half* __restrict__ prh, __half* __restrict__ prl,
               const __half* __restrict__ whT, const __half* __restrict__ wiT,
               const float* __restrict__ bi, const float* __restrict__ bhp,
               __half* __restrict__ oh, __half* __restrict__ ol)
{
    extern __shared__ char dsm[];
    const u32 S = smaddr(dsm);
    const int tid = threadIdx.x, lane = tid & 31, wid = tid >> 5;
    const int row0 = blockIdx.x * 128;
    const int m0 = (wid & 3) * 32, n0 = (wid >> 2) * 64;

    load_bias(dsm, bi, bhp, tid);
    stage128(S + oAH, hh + (size_t)row0 * 128, 128, tid);
    stage128(S + oAL, hl + (size_t)row0 * 128, 128, tid);
    stage128(S + oBH, h2oT, 32, tid);
    stage128(S + oBH + 8192, h2oT + 4096, 32, tid);
    cpcommit(); cpwait0(); __syncthreads();

    // ---- pred GEMM: warp wid handles rows wid*16..+15, all 32 cols ----
    {
        const int pm0 = wid * 16;
        float a4[4][4];
#pragma unroll
        for (int f = 0; f < 4; f++)
#pragma unroll
            for (int i = 0; i < 4; i++) a4[f][i] = 0.0f;
        for (int kc = 0; kc < 8; kc++) {
            u32 ahr[4], alr[4];
            ldmA128(ahr, S + oAH, pm0, lane, kc);
            ldmA128(alr, S + oAL, pm0, lane, kc);
#pragma unroll
            for (int G = 0; G < 2; G++) {
                u32 bh[4], bl[4];
                ldmB128(bh, S + oBH, G * 16, lane, kc);
                ldmB128(bl, S + oBH + 8192, G * 16, lane, kc);
                mmaf(a4[G * 2], ahr, bh);     mmaf(a4[G * 2 + 1], ahr, bh + 2);
                mmaf(a4[G * 2], ahr, bl);     mmaf(a4[G * 2 + 1], ahr, bl + 2);
                mmaf(a4[G * 2], alr, bh);     mmaf(a4[G * 2 + 1], alr, bh + 2);
            }
        }
        const int lr = lane >> 2, lc = 2 * (lane & 3);
#pragma unroll
        for (int f = 0; f < 4; f++)
#pragma unroll
            for (int i = 0; i < 4; i++) {
                int row = pm0 + lr + (i >> 1) * 8;
                int col = f * 8 + lc + (i & 1);
                *(float*)(dsm + oRS + (row * 32 + col) * 4) = a4[f][i] + __ldg(h2ob + col);
            }
    }
    __syncthreads();

    // stage gate-r B (overlaps with softmax below)
    stage128(S + oBH, whT, 128, tid);
    stage128(S + oBL, whT + 16384, 128, tid);
    stage32s(S + oBXH, wiT, tid);
    stage32s(S + oBXL, wiT + 4096, tid);
    cpcommit();

    // softmax: write pred + probs(global) + probs panels (SMEM x)
    if (tid < 128) {
        const int row = tid;
        const float* pr = (const float*)(dsm + oRS + row * 128);
        float v[32], mx = -1e30f;
#pragma unroll
        for (int i = 0; i < 32; i++) { v[i] = pr[i]; mx = fmaxf(mx, v[i]); }
        float e[32], sum = 0.0f;
#pragma unroll
        for (int i = 0; i < 32; i++) { e[i] = __expf(v[i] - mx); sum += e[i]; }
        float inv = __fdividef(1.0f, sum);
        size_t go = (size_t)(row0 + row) * 32;
        float4* pg = (float4*)(pred + go);
#pragma unroll
        for (int q = 0; q < 8; q++)
            pg[q] = make_float4(v[4 * q], v[4 * q + 1], v[4 * q + 2], v[4 * q + 3]);
#pragma unroll
        for (int j = 0; j < 16; j++) {
            float p0 = e[2 * j] * inv, p1 = e[2 * j + 1] * inv;
            __half H0, L0, H1, L1;
            wsplit(p0, H0, L0); wsplit(p1, H1, L1);
            __half2 hh2 = __halves2half2(H0, H1), ll2 = __halves2half2(L0, L1);
            *(__half2*)(prh + go + 2 * j) = hh2;
            *(__half2*)(prl + go + 2 * j) = ll2;
            int k = 2 * j;
            u32 xa = (u32)row * 64u + (u32)((((k >> 3) ^ (row & 3)) << 4)) + (k & 7) * 2;
            *(__half2*)(dsm + oAXH + xa) = hh2;
            *(__half2*)(dsm + oAXL + xa) = ll2;
        }
    }
    __syncthreads();   // probs panels visible before gates

    float acc[16][4];
    gru_gates(dsm, S, whT, wiT, tid, lane, wid, m0, n0, acc);

    // store hidden (hi/lo planes)
    const int lr = lane >> 2, lc = 2 * (lane & 3);
#pragma unroll
    for (int f = 0; f < 16; f++) {
        int colb = n0 + (f & 7) * 8 + lc;
#pragma unroll
        for (int hp = 0; hp < 2; hp++) {
            int row = m0 + (f >> 3) * 16 + lr + hp * 8;
            __half H0, L0, H1, L1;
            wsplit(acc[f][hp * 2], H0, L0); wsplit(acc[f][hp * 2 + 1], H1, L1);
            size_t go = (size_t)(row0 + row) * 128 + colb;
            *(__half2*)(oh + go) = __halves2half2(H0, H1);
            *(__half2*)(ol + go) = __halves2half2(L0, L1);
        }
    }
}

// ===================== grucomb: frat GRU + comb (hF stays on-chip) =====================
__global__ __launch_bounds__(256)
void grucomb_k(const __half* __restrict__ xh, const __half* __restrict__ xl,
               const __half* __restrict__ hh, const __half* __restrict__ hl,
               const __half* __restrict__ whT, const __half* __restrict__ wiT,
               const float* __restrict__ bi, const float* __restrict__ bhp,
               const __half* __restrict__ pah, const __half* __restrict__ pal,
               const __half* __restrict__ ufT, const __half* __restrict__ uaT,
               const float* __restrict__ ufb, const float* __restrict__ uab,
               __half* __restrict__ oh, __half* __restrict__ ol)
{
    extern __shared__ char dsm[];
    const u32 S = smaddr(dsm);
    const int tid = threadIdx.x, lane = tid & 31, wid = tid >> 5;
    const int row0 = blockIdx.x * 128;
    const int m0 = (wid & 3) * 32, n0 = (wid >> 2) * 64;

    load_bias(dsm, bi, bhp, tid);
    stage128(S + oAH, hh + (size_t)row0 * 128, 128, tid);
    stage128(S + oAL, hl + (size_t)row0 * 128, 128, tid);
    stage32s(S + oAXH, xh + (size_t)row0 * 32, tid);
    stage32s(S + oAXL, xl + (size_t)row0 * 32, tid);
    stage128(S + oBH, whT, 128, tid);
    stage128(S + oBL, whT + 16384, 128, tid);
    stage32s(S + oBXH, wiT, tid);
    stage32s(S + oBXL, wiT + 4096, tid);
    cpcommit();

    float acc[16][4];
    gru_gates(dsm, S, whT, wiT, tid, lane, wid, m0, n0, acc);   // acc = hF values

    __syncthreads();   // all warps done reading gate-n B / RS / ZS / AH / AL

    // hF -> SMEM panels at oBH/oBL (stage128 layout); stage uf -> RS/ZS, parent hidden -> AH/AL
    const int lr = lane >> 2, lc = 2 * (lane & 3);
#pragma unroll
    for (int f = 0; f < 16; f++) {
        int colb = n0 + (f & 7) * 8 + lc;
#pragma unroll
        for (int hp = 0; hp < 2; hp++) {
            int row = m0 + (f >> 3) * 16 + lr + hp * 8;
            __half H0, L0, H1, L1;
            wsplit(acc[f][hp * 2], H0, L0); wsplit(acc[f][hp * 2 + 1], H1, L1);
            u32 aoff = (u32)row * 256u + (u32)((((colb >> 3) ^ (row & 7)) << 4)) + (colb & 7) * 2;
            *(__half2*)(dsm + oBH + aoff) = __halves2half2(H0, H1);
            *(__half2*)(dsm + oBL + aoff) = __halves2half2(L0, L1);
        }
    }
    stage128(S + oRS, ufT, 128, tid);
    stage128(S + oZS, ufT + 16384, 128, tid);
    stage128(S + oAH, pah + (size_t)row0 * 128, 128, tid);
    stage128(S + oAL, pal + (size_t)row0 * 128, 128, tid);
    cpcommit(); cpwait0(); __syncthreads();

    // comb phase 1: hF @ uf
    zacc(acc);
    for (int kc = 0; kc < 8; kc++)
        kstep128(acc, S + oBH, S + oBL, S + oRS, S + oZS, m0, n0, lane, kc);
    __syncthreads();
    stage128(S + oRS, uaT, 128, tid);
    stage128(S + oZS, uaT + 16384, 128, tid);
    cpcommit(); cpwait0(); __syncthreads();
    // comb phase 2: hA_parent @ ua (accumulate)
    for (int kc = 0; kc < 8; kc++)
        kstep128(acc, S + oAH, S + oAL, S + oRS, S + oZS, m0, n0, lane, kc);

    // epilogue: tanh + biases, store
#pragma unroll
    for (int f = 0; f < 16; f++) {
        int colb = n0 + (f & 7) * 8 + lc;
        float b0 = __ldg(ufb + colb) + __ldg(uab + colb);
        float b1 = __ldg(ufb + colb + 1) + __ldg(uab + colb + 1);
#pragma unroll
        for (int hp = 0; hp < 2; hp++) {
            int row = m0 + (f >> 3) * 16 + lr + hp * 8;
            float o0 = ftanh(acc[f][hp * 2] + b0);
            float o1 = ftanh(acc[f][hp * 2 + 1] + b1);
            __half H0, L0, H1, L1;
            wsplit(o0, H0, L0); wsplit(o1, H1, L1);
            size_t go = (size_t)(row0 + row) * 128 + colb;
            *(__half2*)(oh + go) = __halves2half2(H0, H1);
            *(__half2*)(ol + go) = __halves2half2(L0, L1);
        }
    }
}

// ===================== leaf node (R5) =====================
#define nAH 0
#define nAL 32768
#define nBH 65536
#define nBL 73728
#define nPR 81920
#define NODE_DS 98304

__global__ __launch_bounds__(256)
void node_k(const __half* __restrict__ hh, const __half* __restrict__ hl,
            const __half* __restrict__ h2oT, const float* __restrict__ b,
            float* __restrict__ pred, __half* __restrict__ ph, __half* __restrict__ pl)
{
    extern __shared__ char dsm[];
    const u32 S = smaddr(dsm);
    const int tid = threadIdx.x, lane = tid & 31, wid = tid >> 5;
    const int row0 = blockIdx.x * 128;
    const int m0 = wid * 16;

    stage128(S + nAH, hh + (size_t)row0 * 128, 128, tid);
    stage128(S + nAL, hl + (size_t)row0 * 128, 128, tid);
    stage128(S + nBH, h2oT, 32, tid);
    stage128(S + nBL, h2oT + 4096, 32, tid);
    cpcommit(); cpwait0(); __syncthreads();

    float acc[4][4];
#pragma unroll
    for (int f = 0; f < 4; f++)
#pragma unroll
        for (int i = 0; i < 4; i++) acc[f][i] = 0.0f;

    for (int kc = 0; kc < 8; kc++) {
        u32 ahr[4], alr[4];
        ldmA128(ahr, S + nAH, m0, lane, kc);
        ldmA128(alr, S + nAL, m0, lane, kc);
#pragma unroll
        for (int G = 0; G < 2; G++) {
            u32 bh[4], bl[4];
            ldmB128(bh, S + nBH, G * 16, lane, kc);
            ldmB128(bl, S + nBL, G * 16, lane, kc);
            mmaf(acc[G * 2], ahr, bh);     mmaf(acc[G * 2 + 1], ahr, bh + 2);
            mmaf(acc[G * 2], ahr, bl);     mmaf(acc[G * 2 + 1], ahr, bl + 2);
            mmaf(acc[G * 2], alr, bh);     mmaf(acc[G * 2 + 1], alr, bh + 2);
        }
    }
    const int lr = lane >> 2, lc = 2 * (lane & 3);
#pragma unroll
    for (int f = 0; f < 4; f++)
#pragma unroll
        for (int i = 0; i < 4; i++) {
            int row = m0 + lr + (i >> 1) * 8;
            int col = f * 8 + lc + (i & 1);
            *(float*)(dsm + nPR + (row * 32 + col) * 4) = acc[f][i] + __ldg(b + col);
        }
    __syncthreads();
    if (tid < 128) {
        int row = tid;
        const float* pr = (const float*)(dsm + nPR + row * 128);
        float v[32], mx = -1e30f;
#pragma unroll
        for (int i = 0; i < 32; i++) { v[i] = pr[i]; mx = fmaxf(mx, v[i]); }
        float e[32], sum = 0.0f;
#pragma unroll
        for (int i = 0; i < 32; i++) { e[i] = __expf(v[i] - mx); sum += e[i]; }
        float inv = __fdividef(1.0f, sum);
        size_t go = (size_t)(row0 + row) * 32;
        float4* pg = (float4*)(pred + go);
#pragma unroll
        for (int q = 0; q < 8; q++)
            pg[q] = make_float4(v[4 * q], v[4 * q + 1], v[4 * q + 2], v[4 * q + 3]);
#pragma unroll
        for (int j = 0; j < 16; j++) {
            float p0 = e[2 * j] * inv, p1 = e[2 * j + 1] * inv;
            __half H0, L0, H1, L1;
            wsplit(p0, H0, L0); wsplit(p1, H1, L1);
            *(__half2*)(ph + go + 2 * j) = __halves2half2(H0, H1);
            *(__half2*)(pl + go + 2 * j) = __halves2half2(L0, L1);
        }
    }
}

// ===================== host =====================
namespace {
struct LCtx {
    const __half* wt;
    const float *h2o_b;
    const float *anc_bi, *anc_bh, *frat_bi, *frat_bh;
    const float *ua_b, *uf_b;
    __half *hAh, *hAl, *prh, *prl;
    float* out;
    int idx;
};

void rec(LCtx& c, int L, int d)
{
    size_t hL = (size_t)L * BATCH * HD, hL1 = (size_t)(L + 1) * BATCH * HD;
    size_t pL = (size_t)L * BATCH * OD, pL1 = (size_t)(L + 1) * BATCH * OD;

    if (d == 0) {
        node_k<<<BATCH / 128, 256, NODE_DS>>>(c.hAh + hL, c.hAl + hL,
                                              c.wt + W_H2O, c.h2o_b,
                                              c.out + (size_t)c.idx * BATCH * OD,
                                              c.prh + pL, c.prl + pL);
        c.idx++;
        return;
    }

    nodegru_k<<<BATCH / 128, 256, FUSE_DS>>>(c.hAh + hL, c.hAl + hL,
                                             c.wt + W_H2O, c.h2o_b,
                                             c.out + (size_t)c.idx * BATCH * OD,
                                             c.prh + pL, c.prl + pL,
                                             c.wt + W_ANC_WH, c.wt + W_ANC_WI,
                                             c.anc_bi, c.anc_bh,
                                             c.hAh + hL1, c.hAl + hL1);
    c.idx++;
    rec(c, L + 1, d - 1);

    grucomb_k<<<BATCH / 128, 256, FUSE_DS>>>(c.prh + pL1, c.prl + pL1,
                                             c.hAh + hL1, c.hAl + hL1,
                                             c.wt + W_FRAT_WH, c.wt + W_FRAT_WI,
                                             c.frat_bi, c.frat_bh,
                                             c.hAh + hL, c.hAl + hL,
                                             c.wt + W_UF, c.wt + W_UA,
                                             c.uf_b, c.ua_b,
                                             c.hAh + hL1, c.hAl + hL1);
    rec(c, L + 1, d - 1);
}
} // namespace

extern "C" void kernel_launch(void* const* d_in, const int* in_sizes, int n_in,
                              void* d_out, int out_size)
{
    const float* z       = (const float*)d_in[0];
    const float* z2h_w   = (const float*)d_in[1];
    const float* z2h_b   = (const float*)d_in[2];
    const float* h2o_w   = (const float*)d_in[3];
    const float* h2o_b   = (const float*)d_in[4];
    const float* anc_wi  = (const float*)d_in[5];
    const float* anc_wh  = (const float*)d_in[6];
    const float* anc_bi  = (const float*)d_in[7];
    const float* anc_bh  = (const float*)d_in[8];
    const float* frat_wi = (const float*)d_in[9];
    const float* frat_wh = (const float*)d_in[10];
    const float* frat_bi = (const float*)d_in[11];
    const float* frat_bh = (const float*)d_in[12];
    const float* ua_w    = (const float*)d_in[13];
    const float* ua_b    = (const float*)d_in[14];
    const float* uf_w    = (const float*)d_in[15];
    const float* uf_b    = (const float*)d_in[16];

    cudaFuncSetAttribute(nodegru_k, cudaFuncAttributeMaxDynamicSharedMemorySize, FUSE_DS);
    cudaFuncSetAttribute(grucomb_k, cudaFuncAttributeMaxDynamicSharedMemorySize, FUSE_DS);
    cudaFuncSetAttribute(node_k,    cudaFuncAttributeMaxDynamicSharedMemorySize, NODE_DS);

    __half *wt, *hAh, *hAl, *prh, *prl;
    cudaGetSymbolAddress((void**)&wt, g_wt);
    cudaGetSymbolAddress((void**)&hAh, g_hAh);
    cudaGetSymbolAddress((void**)&hAl, g_hAl);
    cudaGetSymbolAddress((void**)&prh, g_prh);
    cudaGetSymbolAddress((void**)&prl, g_prl);

    k_prep<<<128, 256>>>(anc_wi, anc_wh, frat_wi, frat_wh, uf_w, ua_w, h2o_w);
    init_k<<<BATCH / 16, 128>>>(z, z2h_w, z2h_b, hAh, hAl);

    LCtx c;
    c.wt = wt; c.h2o_b = h2o_b;
    c.anc_bi = anc_bi; c.anc_bh = anc_bh;
    c.frat_bi = frat_bi; c.frat_bh = frat_bh;
    c.ua_b = ua_b; c.uf_b = uf_b;
    c.hAh = hAh; c.hAl = hAl;
    c.prh = prh; c.prl = prl;
    c.out = (float*)d_out;
    c.idx = 0;
    rec(c, 0, DEPTH);
}

// round 8
// speedup vs baseline: 1.1849x; 1.0514x over previous
#include <cuda_runtime.h>
#include <cuda_fp16.h>
#include <cstdint>

#define BATCH 32768
#define HD 128
#define OD 32
#define DEPTH 5
typedef uint32_t u32;

// ---- weight tile offsets in g_wt (halves) ----
#define W_ANC_WH  0
#define W_FRAT_WH 98304
#define W_ANC_WI  196608
#define W_FRAT_WI 221184
#define W_UF      245760
#define W_UA      278528
#define W_H2O     311296
__device__ __half g_wt[319488];

__device__ __half g_hAh[DEPTH + 1][BATCH * HD];
__device__ __half g_hAl[DEPTH + 1][BATCH * HD];
__device__ __half g_prh[DEPTH + 1][BATCH * OD];
__device__ __half g_prl[DEPTH + 1][BATCH * OD];

// ===================== helpers =====================
__device__ __forceinline__ u32 smaddr(const void* p) {
    u32 a;
    asm("{ .reg .u64 t; cvta.to.shared.u64 t, %1; cvt.u32.u64 %0, t; }" : "=r"(a) : "l"(p));
    return a;
}
__device__ __forceinline__ void cpa16(u32 d, const void* s) {
    asm volatile("cp.async.cg.shared.global [%0], [%1], 16;" :: "r"(d), "l"(s) : "memory");
}
__device__ __forceinline__ void cpcommit() {
    asm volatile("cp.async.commit_group;" ::: "memory");
}
__device__ __forceinline__ void cpwait0() {
    asm volatile("cp.async.wait_group 0;" ::: "memory");
}
__device__ __forceinline__ void ldm4(u32* r, u32 a) {
    asm volatile("ldmatrix.sync.aligned.m8n8.x4.shared.b16 {%0,%1,%2,%3}, [%4];"
                 : "=r"(r[0]), "=r"(r[1]), "=r"(r[2]), "=r"(r[3]) : "r"(a));
}
__device__ __forceinline__ void mmaf(float* c, const u32* a, const u32* b) {
    asm volatile(
        "mma.sync.aligned.m16n8k16.row.col.f32.f16.f16.f32 "
        "{%0,%1,%2,%3},{%4,%5,%6,%7},{%8,%9},{%0,%1,%2,%3};"
        : "+f"(c[0]), "+f"(c[1]), "+f"(c[2]), "+f"(c[3])
        : "r"(a[0]), "r"(a[1]), "r"(a[2]), "r"(a[3]), "r"(b[0]), "r"(b[1]));
}
__device__ __forceinline__ float fsig(float x)  { return __fdividef(1.0f, 1.0f + __expf(-x)); }
__device__ __forceinline__ float ftanh(float x) { float u = __expf(2.0f * x); return 1.0f - __fdividef(2.0f, u + 1.0f); }
__device__ __forceinline__ void wsplit(float v, __half& h, __half& l) {
    h = __float2half_rn(v);
    l = __float2half_rn(v - __half2float(h));
}

__device__ __forceinline__ void ldmA128(u32* r, u32 base, int m0, int lane, int kc) {
    int row = m0 + (lane & 15), c16 = 2 * kc + (lane >> 4);
    ldm4(r, base + (u32)row * 256u + (u32)((c16 ^ (row & 7)) << 4));
}
__device__ __forceinline__ void ldmB128(u32* r, u32 base, int n0, int lane, int kc) {
    int row = n0 + (lane & 7) + ((lane >> 4) << 3), c16 = 2 * kc + ((lane >> 3) & 1);
    ldm4(r, base + (u32)row * 256u + (u32)((c16 ^ (row & 7)) << 4));
}
__device__ __forceinline__ void ldmA32(u32* r, u32 base, int m0, int lane, int kc) {
    int row = m0 + (lane & 15), c4 = 2 * kc + (lane >> 4);
    ldm4(r, base + (u32)row * 64u + (u32)((c4 ^ (row & 3)) << 4));
}
__device__ __forceinline__ void ldmB32(u32* r, u32 base, int n0, int lane, int kc) {
    int row = n0 + (lane & 7) + ((lane >> 4) << 3), c4 = 2 * kc + ((lane >> 3) & 1);
    ldm4(r, base + (u32)row * 64u + (u32)((c4 ^ (row & 3)) << 4));
}

// ---- 32x32 warp tile, 3-term hi/lo, one k16 chunk ----
// acc layout: acc[mf*4 + G*2 + half][4]
__device__ __forceinline__ void kstep128w(float (*acc)[4], u32 AH, u32 AL, u32 BH, u32 BL,
                                          int m0, int n0, int lane, int kc) {
    u32 a[4][4];
    ldmA128(a[0], AH, m0, lane, kc);      ldmA128(a[1], AH, m0 + 16, lane, kc);
    ldmA128(a[2], AL, m0, lane, kc);      ldmA128(a[3], AL, m0 + 16, lane, kc);
#pragma unroll
    for (int G = 0; G < 2; G++) {
        u32 bh[4], bl[4];
        ldmB128(bh, BH, n0 + G * 16, lane, kc);
        ldmB128(bl, BL, n0 + G * 16, lane, kc);
#pragma unroll
        for (int mf = 0; mf < 2; mf++) {
            float* c0 = acc[mf * 4 + G * 2];
            float* c1 = acc[mf * 4 + G * 2 + 1];
            mmaf(c0, a[mf], bh);     mmaf(c1, a[mf], bh + 2);
            mmaf(c0, a[mf], bl);     mmaf(c1, a[mf], bl + 2);
            mmaf(c0, a[2 + mf], bh); mmaf(c1, a[2 + mf], bh + 2);
        }
    }
}
__device__ __forceinline__ void kstep32w(float (*acc)[4], u32 AH, u32 AL, u32 BH, u32 BL,
                                         int m0, int n0, int lane, int kc) {
    u32 a[4][4];
    ldmA32(a[0], AH, m0, lane, kc);      ldmA32(a[1], AH, m0 + 16, lane, kc);
    ldmA32(a[2], AL, m0, lane, kc);      ldmA32(a[3], AL, m0 + 16, lane, kc);
#pragma unroll
    for (int G = 0; G < 2; G++) {
        u32 bh[4], bl[4];
        ldmB32(bh, BH, n0 + G * 16, lane, kc);
        ldmB32(bl, BL, n0 + G * 16, lane, kc);
#pragma unroll
        for (int mf = 0; mf < 2; mf++) {
            float* c0 = acc[mf * 4 + G * 2];
            float* c1 = acc[mf * 4 + G * 2 + 1];
            mmaf(c0, a[mf], bh);     mmaf(c1, a[mf], bh + 2);
            mmaf(c0, a[mf], bl);     mmaf(c1, a[mf], bl + 2);
            mmaf(c0, a[2 + mf], bh); mmaf(c1, a[2 + mf], bh + 2);
        }
    }
}
__device__ __forceinline__ void zacc8(float (*acc)[4]) {
#pragma unroll
    for (int f = 0; f < 8; f++)
#pragma unroll
        for (int i = 0; i < 4; i++) acc[f][i] = 0.0f;
}

__device__ __forceinline__ void stage128(u32 dst, const __half* src, int rows, int tid, int nt) {
    for (int i = tid; i < rows * 16; i += nt) {
        int r = i >> 4, c = i & 15;
        cpa16(dst + (u32)r * 256u + (u32)((c ^ (r & 7)) << 4), src + (size_t)r * 128 + c * 8);
    }
}
__device__ __forceinline__ void stage32s(u32 dst, const __half* src, int tid, int nt) {
    for (int i = tid; i < 128 * 4; i += nt) {
        int r = i >> 2, c = i & 3;
        cpa16(dst + (u32)r * 64u + (u32)((c ^ (r & 3)) << 4), src + (size_t)r * 32 + c * 8);
    }
}

// ===================== prep =====================
__global__ void k_prep(const float* __restrict__ anc_wi, const float* __restrict__ anc_wh,
                       const float* __restrict__ frat_wi, const float* __restrict__ frat_wh,
                       const float* __restrict__ uf_w, const float* __restrict__ ua_w,
                       const float* __restrict__ h2o_w)
{
    int t = blockIdx.x * blockDim.x + threadIdx.x, NT = gridDim.x * blockDim.x;
    for (int i = t; i < 3 * 16384; i += NT) {
        int g = i >> 14, rem = i & 16383, k = rem >> 7, n = rem & 127;
        int d = g * 32768 + n * 128 + k;
        __half h, l;
        wsplit(anc_wh[i], h, l);  g_wt[W_ANC_WH + d] = h;  g_wt[W_ANC_WH + d + 16384] = l;
        wsplit(frat_wh[i], h, l); g_wt[W_FRAT_WH + d] = h; g_wt[W_FRAT_WH + d + 16384] = l;
    }
    for (int i = t; i < 3 * 4096; i += NT) {
        int g = i >> 12, rem = i & 4095, k = rem >> 7, n = rem & 127;
        int d = g * 8192 + n * 32 + k;
        __half h, l;
        wsplit(anc_wi[i], h, l);  g_wt[W_ANC_WI + d] = h;  g_wt[W_ANC_WI + d + 4096] = l;
        wsplit(frat_wi[i], h, l); g_wt[W_FRAT_WI + d] = h; g_wt[W_FRAT_WI + d + 4096] = l;
    }
    for (int i = t; i < 16384; i += NT) {
        int k = i >> 7, n = i & 127, d = n * 128 + k;
        __half h, l;
        wsplit(uf_w[i], h, l); g_wt[W_UF + d] = h; g_wt[W_UF + d + 16384] = l;
        wsplit(ua_w[i], h, l); g_wt[W_UA + d] = h; g_wt[W_UA + d + 16384] = l;
    }
    for (int i = t; i < 4096; i += NT) {
        int k = i >> 5, n = i & 31, d = n * 128 + k;
        __half h, l;
        wsplit(h2o_w[i], h, l); g_wt[W_H2O + d] = h; g_wt[W_H2O + d + 4096] = l;
    }
}

// ===================== init =====================
__global__ __launch_bounds__(128, 4)
void init_k(const float* __restrict__ z, const float* __restrict__ w,
            const float* __restrict__ b, __half* __restrict__ oh, __half* __restrict__ ol)
{
    const int g = threadIdx.x;
    const int row0 = blockIdx.x * 16;
    __shared__ float s[16][HD];
    for (int r = 0; r < 16; r++) s[r][g] = z[(size_t)(row0 + r) * HD + g];
    __syncthreads();
    float a[16];
#pragma unroll
    for (int r = 0; r < 16; r++) a[r] = 0.0f;
    for (int j = 0; j < HD; j++) {
        float wv = __ldg(w + (size_t)j * HD + g);
#pragma unroll
        for (int r = 0; r < 16; r++) a[r] += s[r][j] * wv;
    }
    float bg = __ldg(b + g);
#pragma unroll
    for (int r = 0; r < 16; r++) {
        __half h, l; wsplit(a[r] + bg, h, l);
        size_t o = (size_t)(row0 + r) * HD + g;
        oh[o] = h; ol[o] = l;
    }
}

// ===================== shared SMEM layout for fused kernels =====================
#define oAH  0
#define oAL  32768
#define oAXH 65536
#define oAXL 73728
#define oBH  81920
#define oBL  114688
#define oBXH 147456
#define oBXL 155648
#define oRS  163840
#define oZS  196608
#define oBIA 229376
#define FUSE_DS 231424
#define FT 512   /* threads in fused kernels */

// ---- GRU gate machinery, 16 warps x (32x32) tiles ----
__device__ __forceinline__ void gru_gates(char* dsm, u32 S, const __half* whT, const __half* wiT,
                                          int tid, int lane, int m0, int n0,
                                          float (*acc)[4])
{
    const int lr = lane >> 2, lc = 2 * (lane & 3);
    cpwait0(); __syncthreads();

#pragma unroll 1
    for (int gate = 0; gate < 2; gate++) {
        zacc8(acc);
        for (int kc = 0; kc < 8; kc++)
            kstep128w(acc, S + oAH, S + oAL, S + oBH, S + oBL, m0, n0, lane, kc);
        for (int kc = 0; kc < 2; kc++)
            kstep32w(acc, S + oAXH, S + oAXL, S + oBXH, S + oBXL, m0, n0, lane, kc);
        int oRZ = gate ? oZS : oRS;
#pragma unroll
        for (int f = 0; f < 8; f++) {
            int mf = f >> 2, ng = f & 3;
            int colb = n0 + ng * 8 + lc;
            float b0 = ((const float*)(dsm + oBIA + colb * 16))[gate];
            float b1 = ((const float*)(dsm + oBIA + (colb + 1) * 16))[gate];
#pragma unroll
            for (int hp = 0; hp < 2; hp++) {
                int row = m0 + mf * 16 + lr + hp * 8;
                float v0 = fsig(acc[f][hp * 2] + b0);
                float v1 = fsig(acc[f][hp * 2 + 1] + b1);
                ushort2 u = make_ushort2((unsigned short)(v0 * 65535.f + 0.5f),
                                         (unsigned short)(v1 * 65535.f + 0.5f));
                *(ushort2*)(dsm + oRZ + row * 256 + colb * 2) = u;
            }
        }
        __syncthreads();
        const __half* wh2 = whT + (size_t)(gate + 1) * 32768;
        const __half* wi2 = wiT + (size_t)(gate + 1) * 8192;
        stage128(S + oBH, wh2, 128, tid, FT);
        stage128(S + oBL, wh2 + 16384, 128, tid, FT);
        stage32s(S + oBXH, wi2, tid, FT);
        stage32s(S + oBXL, wi2 + 4096, tid, FT);
        cpcommit(); cpwait0(); __syncthreads();
    }

    // gate n
    zacc8(acc);
    for (int kc = 0; kc < 8; kc++)
        kstep128w(acc, S + oAH, S + oAL, S + oBH, S + oBL, m0, n0, lane, kc);
    float acc2[8][4];
    zacc8(acc2);
    for (int kc = 0; kc < 2; kc++)
        kstep32w(acc2, S + oAXH, S + oAXL, S + oBXH, S + oBXL, m0, n0, lane, kc);

    // epilogue: final hidden values into acc
    const float Q = 1.0f / 65535.0f;
#pragma unroll
    for (int f = 0; f < 8; f++) {
        int mf = f >> 2, ng = f & 3;
        int colb = n0 + ng * 8 + lc;
        const float* bp = (const float*)(dsm + oBIA + colb * 16);
        const float* bq = (const float*)(dsm + oBIA + (colb + 1) * 16);
#pragma unroll
        for (int hp = 0; hp < 2; hp++) {
            int row = m0 + mf * 16 + lr + hp * 8;
            ushort2 r2 = *(ushort2*)(dsm + oRS + row * 256 + colb * 2);
            ushort2 z2 = *(ushort2*)(dsm + oZS + row * 256 + colb * 2);
            u32 aoff = (u32)row * 256u + (u32)((((colb >> 3) ^ (row & 7)) << 4)) + (colb & 7) * 2;
            __half2 hhv = *(__half2*)(dsm + oAH + aoff);
            __half2 hlv = *(__half2*)(dsm + oAL + aoff);
            float rr0 = r2.x * Q, rr1 = r2.y * Q;
            float zz0 = z2.x * Q, zz1 = z2.y * Q;
            float nn0 = ftanh(acc2[f][hp * 2]     + bp[3] + rr0 * (acc[f][hp * 2]     + bp[2]));
            float nn1 = ftanh(acc2[f][hp * 2 + 1] + bq[3] + rr1 * (acc[f][hp * 2 + 1] + bq[2]));
            float h0 = __half2float(__low2half(hhv)) + __half2float(__low2half(hlv));
            float h1 = __half2float(__high2half(hhv)) + __half2float(__high2half(hlv));
            acc[f][hp * 2]     = (1.0f - zz0) * nn0 + zz0 * h0;
            acc[f][hp * 2 + 1] = (1.0f - zz1) * nn1 + zz1 * h1;
        }
    }
}

__device__ __forceinline__ void load_bias(char* dsm, const float* bi, const float* bhp, int tid) {
    if (tid < 128) {
        float4 bv = make_float4(__ldg(bi + tid) + __ldg(bhp + tid),
                                __ldg(bi + 128 + tid) + __ldg(bhp + 128 + tid),
                                __ldg(bhp + 256 + tid), __ldg(bi + 256 + tid));
        *(float4*)(dsm + oBIA + tid * 16) = bv;
    }
}

// ===================== nodegru: node(pred+softmax) + anc GRU =====================
__global__ __launch_bounds__(FT, 1)
void nodegru_k(const __half* __restrict__ hh, const __half* __restrict__ hl,
               const __half* __restrict__ h2oT, const float* __restrict__ h2ob,
               float* __restrict__ pred, __half* __restrict__ prh, __half* __restrict__ prl,
               const __half* __restrict__ whT, const __half* __restrict__ wiT,
               const float* __restrict__ bi, const float* __restrict__ bhp,
               __half* __restrict__ oh, __half* __restrict__ ol)
{
    extern __shared__ char dsm[];
    const u32 S = smaddr(dsm);
    const int tid = threadIdx.x, lane = tid & 31, wid = tid >> 5;
    const int row0 = blockIdx.x * 128;
    const int m0 = (wid & 3) * 32, n0 = (wid >> 2) * 32;

    load_bias(dsm, bi, bhp, tid);
    stage128(S + oAH, hh + (size_t)row0 * 128, 128, tid, FT);
    stage128(S + oAL, hl + (size_t)row0 * 128, 128, tid, FT);
    stage128(S + oBH, h2oT, 32, tid, FT);
    stage128(S + oBH + 8192, h2oT + 4096, 32, tid, FT);
    cpcommit(); cpwait0(); __syncthreads();

    // ---- pred GEMM: 16 warps = 8 row groups x 2 col halves ----
    {
        const int pm0 = (wid & 7) * 16, Gp = wid >> 3;
        float a4[2][4];
#pragma unroll
        for (int f = 0; f < 2; f++)
#pragma unroll
            for (int i = 0; i < 4; i++) a4[f][i] = 0.0f;
        for (int kc = 0; kc < 8; kc++) {
            u32 ahr[4], alr[4], bh[4], bl[4];
            ldmA128(ahr, S + oAH, pm0, lane, kc);
            ldmA128(alr, S + oAL, pm0, lane, kc);
            ldmB128(bh, S + oBH, Gp * 16, lane, kc);
            ldmB128(bl, S + oBH + 8192, Gp * 16, lane, kc);
            mmaf(a4[0], ahr, bh);  mmaf(a4[1], ahr, bh + 2);
            mmaf(a4[0], ahr, bl);  mmaf(a4[1], ahr, bl + 2);
            mmaf(a4[0], alr, bh);  mmaf(a4[1], alr, bh + 2);
        }
        const int lr = lane >> 2, lc = 2 * (lane & 3);
#pragma unroll
        for (int f = 0; f < 2; f++)
#pragma unroll
            for (int i = 0; i < 4; i++) {
                int row = pm0 + lr + (i >> 1) * 8;
                int col = Gp * 16 + f * 8 + lc + (i & 1);
                *(float*)(dsm + oRS + (row * 32 + col) * 4) = a4[f][i] + __ldg(h2ob + col);
            }
    }
    __syncthreads();

    // stage gate-r B (overlaps with softmax below)
    stage128(S + oBH, whT, 128, tid, FT);
    stage128(S + oBL, whT + 16384, 128, tid, FT);
    stage32s(S + oBXH, wiT, tid, FT);
    stage32s(S + oBXL, wiT + 4096, tid, FT);
    cpcommit();

    // softmax: write pred + probs(global) + probs panels (SMEM x)
    if (tid < 128) {
        const int row = tid;
        const float* pr = (const float*)(dsm + oRS + row * 128);
        float v[32], mx = -1e30f;
#pragma unroll
        for (int i = 0; i < 32; i++) { v[i] = pr[i]; mx = fmaxf(mx, v[i]); }
        float e[32], sum = 0.0f;
#pragma unroll
        for (int i = 0; i < 32; i++) { e[i] = __expf(v[i] - mx); sum += e[i]; }
        float inv = __fdividef(1.0f, sum);
        size_t go = (size_t)(row0 + row) * 32;
        float4* pg = (float4*)(pred + go);
#pragma unroll
        for (int q = 0; q < 8; q++)
            pg[q] = make_float4(v[4 * q], v[4 * q + 1], v[4 * q + 2], v[4 * q + 3]);
#pragma unroll
        for (int j = 0; j < 16; j++) {
            float p0 = e[2 * j] * inv, p1 = e[2 * j + 1] * inv;
            __half H0, L0, H1, L1;
            wsplit(p0, H0, L0); wsplit(p1, H1, L1);
            __half2 hh2 = __halves2half2(H0, H1), ll2 = __halves2half2(L0, L1);
            *(__half2*)(prh + go + 2 * j) = hh2;
            *(__half2*)(prl + go + 2 * j) = ll2;
            int k = 2 * j;
            u32 xa = (u32)row * 64u + (u32)((((k >> 3) ^ (row & 3)) << 4)) + (k & 7) * 2;
            *(__half2*)(dsm + oAXH + xa) = hh2;
            *(__half2*)(dsm + oAXL + xa) = ll2;
        }
    }
    __syncthreads();

    float acc[8][4];
    gru_gates(dsm, S, whT, wiT, tid, lane, m0, n0, acc);

    // store hidden (hi/lo planes)
    const int lr = lane >> 2, lc = 2 * (lane & 3);
#pragma unroll
    for (int f = 0; f < 8; f++) {
        int colb = n0 + (f & 3) * 8 + lc;
#pragma unroll
        for (int hp = 0; hp < 2; hp++) {
            int row = m0 + (f >> 2) * 16 + lr + hp * 8;
            __half H0, L0, H1, L1;
            wsplit(acc[f][hp * 2], H0, L0); wsplit(acc[f][hp * 2 + 1], H1, L1);
            size_t go = (size_t)(row0 + row) * 128 + colb;
            *(__half2*)(oh + go) = __halves2half2(H0, H1);
            *(__half2*)(ol + go) = __halves2half2(L0, L1);
        }
    }
}

// ===================== grucomb: frat GRU + comb (hF stays on-chip) =====================
__global__ __launch_bounds__(FT, 1)
void grucomb_k(const __half* __restrict__ xh, const __half* __restrict__ xl,
               const __half* __restrict__ hh, const __half* __restrict__ hl,
               const __half* __restrict__ whT, const __half* __restrict__ wiT,
               const float* __restrict__ bi, const float* __restrict__ bhp,
               const __half* __restrict__ pah, const __half* __restrict__ pal,
               const __half* __restrict__ ufT, const __half* __restrict__ uaT,
               const float* __restrict__ ufb, const float* __restrict__ uab,
               __half* __restrict__ oh, __half* __restrict__ ol)
{
    extern __shared__ char dsm[];
    const u32 S = smaddr(dsm);
    const int tid = threadIdx.x, lane = tid & 31, wid = tid >> 5;
    const int row0 = blockIdx.x * 128;
    const int m0 = (wid & 3) * 32, n0 = (wid >> 2) * 32;

    load_bias(dsm, bi, bhp, tid);
    stage128(S + oAH, hh + (size_t)row0 * 128, 128, tid, FT);
    stage128(S + oAL, hl + (size_t)row0 * 128, 128, tid, FT);
    stage32s(S + oAXH, xh + (size_t)row0 * 32, tid, FT);
    stage32s(S + oAXL, xl + (size_t)row0 * 32, tid, FT);
    stage128(S + oBH, whT, 128, tid, FT);
    stage128(S + oBL, whT + 16384, 128, tid, FT);
    stage32s(S + oBXH, wiT, tid, FT);
    stage32s(S + oBXL, wiT + 4096, tid, FT);
    cpcommit();

    float acc[8][4];
    gru_gates(dsm, S, whT, wiT, tid, lane, m0, n0, acc);   // acc = hF values

    __syncthreads();

    // hF -> SMEM panels at oBH/oBL; stage uf -> RS/ZS, parent hidden -> AH/AL
    const int lr = lane >> 2, lc = 2 * (lane & 3);
#pragma unroll
    for (int f = 0; f < 8; f++) {
        int colb = n0 + (f & 3) * 8 + lc;
#pragma unroll
        for (int hp = 0; hp < 2; hp++) {
            int row = m0 + (f >> 2) * 16 + lr + hp * 8;
            __half H0, L0, H1, L1;
            wsplit(acc[f][hp * 2], H0, L0); wsplit(acc[f][hp * 2 + 1], H1, L1);
            u32 aoff = (u32)row * 256u + (u32)((((colb >> 3) ^ (row & 7)) << 4)) + (colb & 7) * 2;
            *(__half2*)(dsm + oBH + aoff) = __halves2half2(H0, H1);
            *(__half2*)(dsm + oBL + aoff) = __halves2half2(L0, L1);
        }
    }
    stage128(S + oRS, ufT, 128, tid, FT);
    stage128(S + oZS, ufT + 16384, 128, tid, FT);
    stage128(S + oAH, pah + (size_t)row0 * 128, 128, tid, FT);
    stage128(S + oAL, pal + (size_t)row0 * 128, 128, tid, FT);
    cpcommit(); cpwait0(); __syncthreads();

    // comb phase 1: hF @ uf
    zacc8(acc);
    for (int kc = 0; kc < 8; kc++)
        kstep128w(acc, S + oBH, S + oBL, S + oRS, S + oZS, m0, n0, lane, kc);
    __syncthreads();
    stage128(S + oRS, uaT, 128, tid, FT);
    stage128(S + oZS, uaT + 16384, 128, tid, FT);
    cpcommit(); cpwait0(); __syncthreads();
    // comb phase 2: hA_parent @ ua (accumulate)
    for (int kc = 0; kc < 8; kc++)
        kstep128w(acc, S + oAH, S + oAL, S + oRS, S + oZS, m0, n0, lane, kc);

    // epilogue
#pragma unroll
    for (int f = 0; f < 8; f++) {
        int colb = n0 + (f & 3) * 8 + lc;
        float b0 = __ldg(ufb + colb) + __ldg(uab + colb);
        float b1 = __ldg(ufb + colb + 1) + __ldg(uab + colb + 1);
#pragma unroll
        for (int hp = 0; hp < 2; hp++) {
            int row = m0 + (f >> 2) * 16 + lr + hp * 8;
            float o0 = ftanh(acc[f][hp * 2] + b0);
            float o1 = ftanh(acc[f][hp * 2 + 1] + b1);
            __half H0, L0, H1, L1;
            wsplit(o0, H0, L0); wsplit(o1, H1, L1);
            size_t go = (size_t)(row0 + row) * 128 + colb;
            *(__half2*)(oh + go) = __halves2half2(H0, H1);
            *(__half2*)(ol + go) = __halves2half2(L0, L1);
        }
    }
}

// ===================== leaf node (R5, unchanged) =====================
#define nAH 0
#define nAL 32768
#define nBH 65536
#define nBL 73728
#define nPR 81920
#define NODE_DS 98304

__global__ __launch_bounds__(256)
void node_k(const __half* __restrict__ hh, const __half* __restrict__ hl,
            const __half* __restrict__ h2oT, const float* __restrict__ b,
            float* __restrict__ pred, __half* __restrict__ ph, __half* __restrict__ pl)
{
    extern __shared__ char dsm[];
    const u32 S = smaddr(dsm);
    const int tid = threadIdx.x, lane = tid & 31, wid = tid >> 5;
    const int row0 = blockIdx.x * 128;
    const int m0 = wid * 16;

    stage128(S + nAH, hh + (size_t)row0 * 128, 128, tid, 256);
    stage128(S + nAL, hl + (size_t)row0 * 128, 128, tid, 256);
    stage128(S + nBH, h2oT, 32, tid, 256);
    stage128(S + nBL, h2oT + 4096, 32, tid, 256);
    cpcommit(); cpwait0(); __syncthreads();

    float acc[4][4];
#pragma unroll
    for (int f = 0; f < 4; f++)
#pragma unroll
        for (int i = 0; i < 4; i++) acc[f][i] = 0.0f;

    for (int kc = 0; kc < 8; kc++) {
        u32 ahr[4], alr[4];
        ldmA128(ahr, S + nAH, m0, lane, kc);
        ldmA128(alr, S + nAL, m0, lane, kc);
#pragma unroll
        for (int G = 0; G < 2; G++) {
            u32 bh[4], bl[4];
            ldmB128(bh, S + nBH, G * 16, lane, kc);
            ldmB128(bl, S + nBL, G * 16, lane, kc);
            mmaf(acc[G * 2], ahr, bh);     mmaf(acc[G * 2 + 1], ahr, bh + 2);
            mmaf(acc[G * 2], ahr, bl);     mmaf(acc[G * 2 + 1], ahr, bl + 2);
            mmaf(acc[G * 2], alr, bh);     mmaf(acc[G * 2 + 1], alr, bh + 2);
        }
    }
    const int lr = lane >> 2, lc = 2 * (lane & 3);
#pragma unroll
    for (int f = 0; f < 4; f++)
#pragma unroll
        for (int i = 0; i < 4; i++) {
            int row = m0 + lr + (i >> 1) * 8;
            int col = f * 8 + lc + (i & 1);
            *(float*)(dsm + nPR + (row * 32 + col) * 4) = acc[f][i] + __ldg(b + col);
        }
    __syncthreads();
    if (tid < 128) {
        int row = tid;
        const float* pr = (const float*)(dsm + nPR + row * 128);
        float v[32], mx = -1e30f;
#pragma unroll
        for (int i = 0; i < 32; i++) { v[i] = pr[i]; mx = fmaxf(mx, v[i]); }
        float e[32], sum = 0.0f;
#pragma unroll
        for (int i = 0; i < 32; i++) { e[i] = __expf(v[i] - mx); sum += e[i]; }
        float inv = __fdividef(1.0f, sum);
        size_t go = (size_t)(row0 + row) * 32;
        float4* pg = (float4*)(pred + go);
#pragma unroll
        for (int q = 0; q < 8; q++)
            pg[q] = make_float4(v[4 * q], v[4 * q + 1], v[4 * q + 2], v[4 * q + 3]);
#pragma unroll
        for (int j = 0; j < 16; j++) {
            float p0 = e[2 * j] * inv, p1 = e[2 * j + 1] * inv;
            __half H0, L0, H1, L1;
            wsplit(p0, H0, L0); wsplit(p1, H1, L1);
            *(__half2*)(ph + go + 2 * j) = __halves2half2(H0, H1);
            *(__half2*)(pl + go + 2 * j) = __halves2half2(L0, L1);
        }
    }
}

// ===================== host =====================
namespace {
struct LCtx {
    const __half* wt;
    const float *h2o_b;
    const float *anc_bi, *anc_bh, *frat_bi, *frat_bh;
    const float *ua_b, *uf_b;
    __half *hAh, *hAl, *prh, *prl;
    float* out;
    int idx;
};

void rec(LCtx& c, int L, int d)
{
    size_t hL = (size_t)L * BATCH * HD, hL1 = (size_t)(L + 1) * BATCH * HD;
    size_t pL = (size_t)L * BATCH * OD, pL1 = (size_t)(L + 1) * BATCH * OD;

    if (d == 0) {
        node_k<<<BATCH / 128, 256, NODE_DS>>>(c.hAh + hL, c.hAl + hL,
                                              c.wt + W_H2O, c.h2o_b,
                                              c.out + (size_t)c.idx * BATCH * OD,
                                              c.prh + pL, c.prl + pL);
        c.idx++;
        return;
    }

    nodegru_k<<<BATCH / 128, FT, FUSE_DS>>>(c.hAh + hL, c.hAl + hL,
                                            c.wt + W_H2O, c.h2o_b,
                                            c.out + (size_t)c.idx * BATCH * OD,
                                            c.prh + pL, c.prl + pL,
                                            c.wt + W_ANC_WH, c.wt + W_ANC_WI,
                                            c.anc_bi, c.anc_bh,
                                            c.hAh + hL1, c.hAl + hL1);
    c.idx++;
    rec(c, L + 1, d - 1);

    grucomb_k<<<BATCH / 128, FT, FUSE_DS>>>(c.prh + pL1, c.prl + pL1,
                                            c.hAh + hL1, c.hAl + hL1,
                                            c.wt + W_FRAT_WH, c.wt + W_FRAT_WI,
                                            c.frat_bi, c.frat_bh,
                                            c.hAh + hL, c.hAl + hL,
                                            c.wt + W_UF, c.wt + W_UA,
                                            c.uf_b, c.ua_b,
                                            c.hAh + hL1, c.hAl + hL1);
    rec(c, L + 1, d - 1);
}
} // namespace

extern "C" void kernel_launch(void* const* d_in, const int* in_sizes, int n_in,
                              void* d_out, int out_size)
{
    const float* z       = (const float*)d_in[0];
    const float* z2h_w   = (const float*)d_in[1];
    const float* z2h_b   = (const float*)d_in[2];
    const float* h2o_w   = (const float*)d_in[3];
    const float* h2o_b   = (const float*)d_in[4];
    const float* anc_wi  = (const float*)d_in[5];
    const float* anc_wh  = (const float*)d_in[6];
    const float* anc_bi  = (const float*)d_in[7];
    const float* anc_bh  = (const float*)d_in[8];
    const float* frat_wi = (const float*)d_in[9];
    const float* frat_wh = (const float*)d_in[10];
    const float* frat_bi = (const float*)d_in[11];
    const float* frat_bh = (const float*)d_in[12];
    const float* ua_w    = (const float*)d_in[13];
    const float* ua_b    = (const float*)d_in[14];
    const float* uf_w    = (const float*)d_in[15];
    const float* uf_b    = (const float*)d_in[16];

    cudaFuncSetAttribute(nodegru_k, cudaFuncAttributeMaxDynamicSharedMemorySize, FUSE_DS);
    cudaFuncSetAttribute(grucomb_k, cudaFuncAttributeMaxDynamicSharedMemorySize, FUSE_DS);
    cudaFuncSetAttribute(node_k,    cudaFuncAttributeMaxDynamicSharedMemorySize, NODE_DS);

    __half *wt, *hAh, *hAl, *prh, *prl;
    cudaGetSymbolAddress((void**)&wt, g_wt);
    cudaGetSymbolAddress((void**)&hAh, g_hAh);
    cudaGetSymbolAddress((void**)&hAl, g_hAl);
    cudaGetSymbolAddress((void**)&prh, g_prh);
    cudaGetSymbolAddress((void**)&prl, g_prl);

    k_prep<<<128, 256>>>(anc_wi, anc_wh, frat_wi, frat_wh, uf_w, ua_w, h2o_w);
    init_k<<<BATCH / 16, 128>>>(z, z2h_w, z2h_b, hAh, hAl);

    LCtx c;
    c.wt = wt; c.h2o_b = h2o_b;
    c.anc_bi = anc_bi; c.anc_bh = anc_bh;
    c.frat_bi = frat_bi; c.frat_bh = frat_bh;
    c.ua_b = ua_b; c.uf_b = uf_b;
    c.hAh = hAh; c.hAl = hAl;
    c.prh = prh; c.prl = prl;
    c.out = (float*)d_out;
    c.idx = 0;
    rec(c, 0, DEPTH);
}

// round 9
// speedup vs baseline: 1.2266x; 1.0352x over previous
#include <cuda_runtime.h>
#include <cuda_fp16.h>
#include <cstdint>

#define BATCH 32768
#define HD 128
#define OD 32
#define DEPTH 5
typedef uint32_t u32;

// ---- weight tile offsets in g_wt (halves) ----
#define W_ANC_WH  0
#define W_FRAT_WH 98304
#define W_ANC_WI  196608
#define W_FRAT_WI 221184
#define W_UF      245760
#define W_UA      278528
#define W_H2O     311296
__device__ __half g_wt[319488];

__device__ __half g_hAh[DEPTH + 1][BATCH * HD];
__device__ __half g_hAl[DEPTH + 1][BATCH * HD];
__device__ __half g_prh[DEPTH + 1][BATCH * OD];
__device__ __half g_prl[DEPTH + 1][BATCH * OD];

// ===================== helpers =====================
__device__ __forceinline__ u32 smaddr(const void* p) {
    u32 a;
    asm("{ .reg .u64 t; cvta.to.shared.u64 t, %1; cvt.u32.u64 %0, t; }" : "=r"(a) : "l"(p));
    return a;
}
__device__ __forceinline__ void cpa16(u32 d, const void* s) {
    asm volatile("cp.async.cg.shared.global [%0], [%1], 16;" :: "r"(d), "l"(s) : "memory");
}
__device__ __forceinline__ void cpcommit() {
    asm volatile("cp.async.commit_group;" ::: "memory");
}
__device__ __forceinline__ void cpwait0() {
    asm volatile("cp.async.wait_group 0;" ::: "memory");
}
__device__ __forceinline__ void ldm4(u32* r, u32 a) {
    asm volatile("ldmatrix.sync.aligned.m8n8.x4.shared.b16 {%0,%1,%2,%3}, [%4];"
                 : "=r"(r[0]), "=r"(r[1]), "=r"(r[2]), "=r"(r[3]) : "r"(a));
}
__device__ __forceinline__ void mmaf(float* c, const u32* a, const u32* b) {
    asm volatile(
        "mma.sync.aligned.m16n8k16.row.col.f32.f16.f16.f32 "
        "{%0,%1,%2,%3},{%4,%5,%6,%7},{%8,%9},{%0,%1,%2,%3};"
        : "+f"(c[0]), "+f"(c[1]), "+f"(c[2]), "+f"(c[3])
        : "r"(a[0]), "r"(a[1]), "r"(a[2]), "r"(a[3]), "r"(b[0]), "r"(b[1]));
}
__device__ __forceinline__ float fsig(float x)  { return __fdividef(1.0f, 1.0f + __expf(-x)); }
__device__ __forceinline__ float ftanh(float x) { float u = __expf(2.0f * x); return 1.0f - __fdividef(2.0f, u + 1.0f); }
__device__ __forceinline__ void wsplit(float v, __half& h, __half& l) {
    h = __float2half_rn(v);
    l = __float2half_rn(v - __half2float(h));
}

// ---- ldmatrix addressing ----
// A: pitch 256B, XOR (row&7) over 16B chunks
__device__ __forceinline__ void ldmA128(u32* r, u32 base, int m0, int lane, int kc) {
    int row = m0 + (lane & 15), c16 = 2 * kc + (lane >> 4);
    ldm4(r, base + (u32)row * 256u + (u32)((c16 ^ (row & 7)) << 4));
}
// B half-panel: pitch 128B (64 k per panel), kc in 0..3
__device__ __forceinline__ void ldmBh(u32* r, u32 base, int n0, int lane, int kc) {
    int row = n0 + (lane & 7) + ((lane >> 4) << 3), c8 = 2 * kc + ((lane >> 3) & 1);
    ldm4(r, base + (u32)row * 128u + (u32)((c8 ^ (row & 7)) << 4));
}
// K=32 panels: pitch 64B, XOR (row&3)
__device__ __forceinline__ void ldmA32(u32* r, u32 base, int m0, int lane, int kc) {
    int row = m0 + (lane & 15), c4 = 2 * kc + (lane >> 4);
    ldm4(r, base + (u32)row * 64u + (u32)((c4 ^ (row & 3)) << 4));
}
__device__ __forceinline__ void ldmB32(u32* r, u32 base, int n0, int lane, int kc) {
    int row = n0 + (lane & 7) + ((lane >> 4) << 3), c4 = 2 * kc + ((lane >> 3) & 1);
    ldm4(r, base + (u32)row * 64u + (u32)((c4 ^ (row & 3)) << 4));
}

// ---- 32x32 warp tile, 3-term hi/lo, one k16 chunk; B from half panel ----
__device__ __forceinline__ void kstep128h(float (*acc)[4], u32 AH, u32 AL, u32 BH, u32 BL,
                                          int m0, int n0, int lane, int kcA, int kcB) {
    u32 a[4][4];
    ldmA128(a[0], AH, m0, lane, kcA);      ldmA128(a[1], AH, m0 + 16, lane, kcA);
    ldmA128(a[2], AL, m0, lane, kcA);      ldmA128(a[3], AL, m0 + 16, lane, kcA);
#pragma unroll
    for (int G = 0; G < 2; G++) {
        u32 bh[4], bl[4];
        ldmBh(bh, BH, n0 + G * 16, lane, kcB);
        ldmBh(bl, BL, n0 + G * 16, lane, kcB);
#pragma unroll
        for (int mf = 0; mf < 2; mf++) {
            float* c0 = acc[mf * 4 + G * 2];
            float* c1 = acc[mf * 4 + G * 2 + 1];
            mmaf(c0, a[mf], bh);     mmaf(c1, a[mf], bh + 2);
            mmaf(c0, a[mf], bl);     mmaf(c1, a[mf], bl + 2);
            mmaf(c0, a[2 + mf], bh); mmaf(c1, a[2 + mf], bh + 2);
        }
    }
}
__device__ __forceinline__ void kstep32w(float (*acc)[4], u32 AH, u32 AL, u32 BH, u32 BL,
                                         int m0, int n0, int lane, int kc) {
    u32 a[4][4];
    ldmA32(a[0], AH, m0, lane, kc);      ldmA32(a[1], AH, m0 + 16, lane, kc);
    ldmA32(a[2], AL, m0, lane, kc);      ldmA32(a[3], AL, m0 + 16, lane, kc);
#pragma unroll
    for (int G = 0; G < 2; G++) {
        u32 bh[4], bl[4];
        ldmB32(bh, BH, n0 + G * 16, lane, kc);
        ldmB32(bl, BL, n0 + G * 16, lane, kc);
#pragma unroll
        for (int mf = 0; mf < 2; mf++) {
            float* c0 = acc[mf * 4 + G * 2];
            float* c1 = acc[mf * 4 + G * 2 + 1];
            mmaf(c0, a[mf], bh);     mmaf(c1, a[mf], bh + 2);
            mmaf(c0, a[mf], bl);     mmaf(c1, a[mf], bl + 2);
            mmaf(c0, a[2 + mf], bh); mmaf(c1, a[2 + mf], bh + 2);
        }
    }
}
__device__ __forceinline__ void zacc8(float (*acc)[4]) {
#pragma unroll
    for (int f = 0; f < 8; f++)
#pragma unroll
        for (int i = 0; i < 4; i++) acc[f][i] = 0.0f;
}

// ---- staging ----
// A panels: rows x 128 halves, 256B pitch
__device__ __forceinline__ void stage128(u32 dst, const __half* src, int rows, int tid, int nt) {
    for (int i = tid; i < rows * 16; i += nt) {
        int r = i >> 4, c = i & 15;
        cpa16(dst + (u32)r * 256u + (u32)((c ^ (r & 7)) << 4), src + (size_t)r * 128 + c * 8);
    }
}
// B half-panels: rows x 64 halves of a 128-wide source, 128B pitch
__device__ __forceinline__ void stageBh(u32 dst, const __half* src, int rows, int tid, int nt) {
    for (int i = tid; i < rows * 8; i += nt) {
        int r = i >> 3, c = i & 7;
        cpa16(dst + (u32)r * 128u + (u32)((c ^ (r & 7)) << 4), src + (size_t)r * 128 + c * 8);
    }
}
// K=32 panels: rows x 32 halves, 64B pitch
__device__ __forceinline__ void stage32s(u32 dst, const __half* src, int rows, int tid, int nt) {
    for (int i = tid; i < rows * 4; i += nt) {
        int r = i >> 2, c = i & 3;
        cpa16(dst + (u32)r * 64u + (u32)((c ^ (r & 3)) << 4), src + (size_t)r * 32 + c * 8);
    }
}

// ===================== prep =====================
__global__ void k_prep(const float* __restrict__ anc_wi, const float* __restrict__ anc_wh,
                       const float* __restrict__ frat_wi, const float* __restrict__ frat_wh,
                       const float* __restrict__ uf_w, const float* __restrict__ ua_w,
                       const float* __restrict__ h2o_w)
{
    int t = blockIdx.x * blockDim.x + threadIdx.x, NT = gridDim.x * blockDim.x;
    for (int i = t; i < 3 * 16384; i += NT) {
        int g = i >> 14, rem = i & 16383, k = rem >> 7, n = rem & 127;
        int d = g * 32768 + n * 128 + k;
        __half h, l;
        wsplit(anc_wh[i], h, l);  g_wt[W_ANC_WH + d] = h;  g_wt[W_ANC_WH + d + 16384] = l;
        wsplit(frat_wh[i], h, l); g_wt[W_FRAT_WH + d] = h; g_wt[W_FRAT_WH + d + 16384] = l;
    }
    for (int i = t; i < 3 * 4096; i += NT) {
        int g = i >> 12, rem = i & 4095, k = rem >> 7, n = rem & 127;
        int d = g * 8192 + n * 32 + k;
        __half h, l;
        wsplit(anc_wi[i], h, l);  g_wt[W_ANC_WI + d] = h;  g_wt[W_ANC_WI + d + 4096] = l;
        wsplit(frat_wi[i], h, l); g_wt[W_FRAT_WI + d] = h; g_wt[W_FRAT_WI + d + 4096] = l;
    }
    for (int i = t; i < 16384; i += NT) {
        int k = i >> 7, n = i & 127, d = n * 128 + k;
        __half h, l;
        wsplit(uf_w[i], h, l); g_wt[W_UF + d] = h; g_wt[W_UF + d + 16384] = l;
        wsplit(ua_w[i], h, l); g_wt[W_UA + d] = h; g_wt[W_UA + d + 16384] = l;
    }
    for (int i = t; i < 4096; i += NT) {
        int k = i >> 5, n = i & 31, d = n * 128 + k;
        __half h, l;
        wsplit(h2o_w[i], h, l); g_wt[W_H2O + d] = h; g_wt[W_H2O + d + 4096] = l;
    }
}

// ===================== init =====================
__global__ __launch_bounds__(128, 4)
void init_k(const float* __restrict__ z, const float* __restrict__ w,
            const float* __restrict__ b, __half* __restrict__ oh, __half* __restrict__ ol)
{
    const int g = threadIdx.x;
    const int row0 = blockIdx.x * 16;
    __shared__ float s[16][HD];
    for (int r = 0; r < 16; r++) s[r][g] = z[(size_t)(row0 + r) * HD + g];
    __syncthreads();
    float a[16];
#pragma unroll
    for (int r = 0; r < 16; r++) a[r] = 0.0f;
    for (int j = 0; j < HD; j++) {
        float wv = __ldg(w + (size_t)j * HD + g);
#pragma unroll
        for (int r = 0; r < 16; r++) a[r] += s[r][j] * wv;
    }
    float bg = __ldg(b + g);
#pragma unroll
    for (int r = 0; r < 16; r++) {
        __half h, l; wsplit(a[r] + bg, h, l);
        size_t o = (size_t)(row0 + r) * HD + g;
        oh[o] = h; ol[o] = l;
    }
}

// ===================== fused-kernel SMEM layout (64-row tiles) =====================
#define oAH  0
#define oAL  16384
#define oAXH 32768
#define oAXL 36864
#define oBH  40960
#define oBL  57344
#define oBXH 73728
#define oBXL 81920
#define oBIA 90112
#define FUSE_DS 92160

__device__ __forceinline__ void load_bias(char* dsm, const float* bi, const float* bhp, int tid) {
    if (tid < 128) {
        float4 bv = make_float4(__ldg(bi + tid) + __ldg(bhp + tid),
                                __ldg(bi + 128 + tid) + __ldg(bhp + 128 + tid),
                                __ldg(bhp + 256 + tid), __ldg(bi + 256 + tid));
        *(float4*)(dsm + oBIA + tid * 16) = bv;
    }
}

// ---- full GRU body: 8 warps x (32x32) over 64x128; r/z in registers ----
// Precondition: A (oAH/oAL, 64 rows), x (oAXH/oAXL, 64 rows), bias staged;
// gate-r wh half0 (oBH/oBL) + wi_r (oBXH/oBXL) staged & committed, NOT waited.
// Postcondition: acc holds final hidden values (blend done).
__device__ __forceinline__ void gru_body(char* dsm, u32 S, const __half* whT, const __half* wiT,
                                         int tid, int lane, int m0, int n0, float (*acc)[4])
{
    const int lr = lane >> 2, lc = 2 * (lane & 3);
    const float Q = 1.0f / 65535.0f;
    u32 rq[16], zq[16];

    cpwait0(); __syncthreads();

#pragma unroll 1
    for (int gate = 0; gate < 2; gate++) {
        zacc8(acc);
        for (int kc = 0; kc < 4; kc++)
            kstep128h(acc, S + oAH, S + oAL, S + oBH, S + oBL, m0, n0, lane, kc, kc);
        __syncthreads();
        stageBh(S + oBH, whT + (size_t)gate * 32768 + 64, 128, tid, 256);
        stageBh(S + oBL, whT + (size_t)gate * 32768 + 16384 + 64, 128, tid, 256);
        cpcommit(); cpwait0(); __syncthreads();
        for (int kc = 4; kc < 8; kc++)
            kstep128h(acc, S + oAH, S + oAL, S + oBH, S + oBL, m0, n0, lane, kc, kc - 4);
        for (int kc = 0; kc < 2; kc++)
            kstep32w(acc, S + oAXH, S + oAXL, S + oBXH, S + oBXL, m0, n0, lane, kc);
        u32* q = gate ? zq : rq;
#pragma unroll
        for (int f = 0; f < 8; f++) {
            int colb = n0 + (f & 3) * 8 + lc;
            float b0 = ((const float*)(dsm + oBIA + colb * 16))[gate];
            float b1 = ((const float*)(dsm + oBIA + (colb + 1) * 16))[gate];
            q[2 * f]     = (u32)(fsig(acc[f][0] + b0) * 65535.f + 0.5f)
                         | ((u32)(fsig(acc[f][1] + b1) * 65535.f + 0.5f) << 16);
            q[2 * f + 1] = (u32)(fsig(acc[f][2] + b0) * 65535.f + 0.5f)
                         | ((u32)(fsig(acc[f][3] + b1) * 65535.f + 0.5f) << 16);
        }
        __syncthreads();
        stageBh(S + oBH, whT + (size_t)(gate + 1) * 32768, 128, tid, 256);
        stageBh(S + oBL, whT + (size_t)(gate + 1) * 32768 + 16384, 128, tid, 256);
        stage32s(S + oBXH, wiT + (size_t)(gate + 1) * 8192, 128, tid, 256);
        stage32s(S + oBXL, wiT + (size_t)(gate + 1) * 8192 + 4096, 128, tid, 256);
        cpcommit(); cpwait0(); __syncthreads();
    }

    // ---- gate n: gh2 (K=128), fold r, accumulate gi2 (K=32) ----
    zacc8(acc);
    for (int kc = 0; kc < 4; kc++)
        kstep128h(acc, S + oAH, S + oAL, S + oBH, S + oBL, m0, n0, lane, kc, kc);
    __syncthreads();
    stageBh(S + oBH, whT + 2 * 32768 + 64, 128, tid, 256);
    stageBh(S + oBL, whT + 2 * 32768 + 16384 + 64, 128, tid, 256);
    cpcommit(); cpwait0(); __syncthreads();
    for (int kc = 4; kc < 8; kc++)
        kstep128h(acc, S + oAH, S + oAL, S + oBH, S + oBL, m0, n0, lane, kc, kc - 4);
#pragma unroll
    for (int f = 0; f < 8; f++) {
        int colb = n0 + (f & 3) * 8 + lc;
        const float* bp = (const float*)(dsm + oBIA + colb * 16);
        const float* bq = (const float*)(dsm + oBIA + (colb + 1) * 16);
#pragma unroll
        for (int hp = 0; hp < 2; hp++) {
            u32 rv = rq[2 * f + hp];
            acc[f][hp * 2]     = (float)(rv & 0xffffu) * Q * (acc[f][hp * 2]     + bp[2]) + bp[3];
            acc[f][hp * 2 + 1] = (float)(rv >> 16)     * Q * (acc[f][hp * 2 + 1] + bq[2]) + bq[3];
        }
    }
    for (int kc = 0; kc < 2; kc++)
        kstep32w(acc, S + oAXH, S + oAXL, S + oBXH, S + oBXL, m0, n0, lane, kc);

    // ---- blend ----
#pragma unroll
    for (int f = 0; f < 8; f++) {
        int colb = n0 + (f & 3) * 8 + lc;
#pragma unroll
        for (int hp = 0; hp < 2; hp++) {
            int row = m0 + (f >> 2) * 16 + lr + hp * 8;
            u32 zv = zq[2 * f + hp];
            float zz0 = (float)(zv & 0xffffu) * Q, zz1 = (float)(zv >> 16) * Q;
            float nn0 = ftanh(acc[f][hp * 2]), nn1 = ftanh(acc[f][hp * 2 + 1]);
            u32 aoff = (u32)row * 256u + (u32)((((colb >> 3) ^ (row & 7)) << 4)) + (colb & 7) * 2;
            __half2 hhv = *(__half2*)(dsm + oAH + aoff);
            __half2 hlv = *(__half2*)(dsm + oAL + aoff);
            float h0 = __half2float(__low2half(hhv)) + __half2float(__low2half(hlv));
            float h1 = __half2float(__high2half(hhv)) + __half2float(__high2half(hlv));
            acc[f][hp * 2]     = (1.0f - zz0) * nn0 + zz0 * h0;
            acc[f][hp * 2 + 1] = (1.0f - zz1) * nn1 + zz1 * h1;
        }
    }
}

// ===================== nodegru: node(pred+softmax) + anc GRU =====================
__global__ __launch_bounds__(256, 2)
void nodegru_k(const __half* __restrict__ hh, const __half* __restrict__ hl,
               const __half* __restrict__ h2oT, const float* __restrict__ h2ob,
               float* __restrict__ pred, __half* __restrict__ prh, __half* __restrict__ prl,
               const __half* __restrict__ whT, const __half* __restrict__ wiT,
               const float* __restrict__ bi, const float* __restrict__ bhp,
               __half* __restrict__ oh, __half* __restrict__ ol)
{
    extern __shared__ char dsm[];
    const u32 S = smaddr(dsm);
    const int tid = threadIdx.x, lane = tid & 31, wid = tid >> 5;
    const int row0 = blockIdx.x * 64;
    const int m0 = (wid & 1) * 32, n0 = (wid >> 1) * 32;

    load_bias(dsm, bi, bhp, tid);
    stage128(S + oAH, hh + (size_t)row0 * 128, 64, tid, 256);
    stage128(S + oAL, hl + (size_t)row0 * 128, 64, tid, 256);
    // h2o in B region: hi halves at oBH, oBH+4096 ; lo at oBL, oBL+4096
    stageBh(S + oBH, h2oT, 32, tid, 256);
    stageBh(S + oBH + 4096, h2oT + 64, 32, tid, 256);
    stageBh(S + oBL, h2oT + 4096, 32, tid, 256);
    stageBh(S + oBL + 4096, h2oT + 4096 + 64, 32, tid, 256);
    cpcommit(); cpwait0(); __syncthreads();

    // ---- pred GEMM: 8 warps = 4 row groups x 2 col halves ----
    {
        const int pm0 = (wid & 3) * 16, Gp = wid >> 2;
        float a4[2][4];
#pragma unroll
        for (int f = 0; f < 2; f++)
#pragma unroll
            for (int i = 0; i < 4; i++) a4[f][i] = 0.0f;
        for (int kc = 0; kc < 8; kc++) {
            int half = kc >> 2, kb = kc & 3;
            u32 ahr[4], alr[4], bh[4], bl[4];
            ldmA128(ahr, S + oAH, pm0, lane, kc);
            ldmA128(alr, S + oAL, pm0, lane, kc);
            ldmBh(bh, S + oBH + half * 4096, Gp * 16, lane, kb);
            ldmBh(bl, S + oBL + half * 4096, Gp * 16, lane, kb);
            mmaf(a4[0], ahr, bh);  mmaf(a4[1], ahr, bh + 2);
            mmaf(a4[0], ahr, bl);  mmaf(a4[1], ahr, bl + 2);
            mmaf(a4[0], alr, bh);  mmaf(a4[1], alr, bh + 2);
        }
        const int lr = lane >> 2, lc = 2 * (lane & 3);
#pragma unroll
        for (int f = 0; f < 2; f++)
#pragma unroll
            for (int i = 0; i < 4; i++) {
                int row = pm0 + lr + (i >> 1) * 8;
                int col = Gp * 16 + f * 8 + lc + (i & 1);
                *(float*)(dsm + oAXH + (row * 32 + col) * 4) = a4[f][i] + __ldg(h2ob + col);
            }
    }
    __syncthreads();

    // stage gate-r weights (B region free now; scratch lives in AX region)
    stageBh(S + oBH, whT, 128, tid, 256);
    stageBh(S + oBL, whT + 16384, 128, tid, 256);
    stage32s(S + oBXH, wiT, 128, tid, 256);
    stage32s(S + oBXL, wiT + 4096, 128, tid, 256);
    cpcommit();

    // softmax: read scratch into regs, sync, then write probs (over scratch)
    float v[32];
    const bool act = (tid < 64);
    if (act) {
        const float* pr = (const float*)(dsm + oAXH + tid * 128);
#pragma unroll
        for (int i = 0; i < 32; i++) v[i] = pr[i];
    }
    __syncthreads();
    if (act) {
        const int row = tid;
        float mx = -1e30f;
#pragma unroll
        for (int i = 0; i < 32; i++) mx = fmaxf(mx, v[i]);
        float e[32], sum = 0.0f;
#pragma unroll
        for (int i = 0; i < 32; i++) { e[i] = __expf(v[i] - mx); sum += e[i]; }
        float inv = __fdividef(1.0f, sum);
        size_t go = (size_t)(row0 + row) * 32;
        float4* pg = (float4*)(pred + go);
#pragma unroll
        for (int q = 0; q < 8; q++)
            pg[q] = make_float4(v[4 * q], v[4 * q + 1], v[4 * q + 2], v[4 * q + 3]);
#pragma unroll
        for (int j = 0; j < 16; j++) {
            float p0 = e[2 * j] * inv, p1 = e[2 * j + 1] * inv;
            __half H0, L0, H1, L1;
            wsplit(p0, H0, L0); wsplit(p1, H1, L1);
            __half2 hh2 = __halves2half2(H0, H1), ll2 = __halves2half2(L0, L1);
            *(__half2*)(prh + go + 2 * j) = hh2;
            *(__half2*)(prl + go + 2 * j) = ll2;
            int k = 2 * j;
            u32 xa = (u32)row * 64u + (u32)((((k >> 3) ^ (row & 3)) << 4)) + (k & 7) * 2;
            *(__half2*)(dsm + oAXH + xa) = hh2;
            *(__half2*)(dsm + oAXL + xa) = ll2;
        }
    }
    __syncthreads();

    float acc[8][4];
    gru_body(dsm, S, whT, wiT, tid, lane, m0, n0, acc);

    // store hidden
    const int lr = lane >> 2, lc = 2 * (lane & 3);
#pragma unroll
    for (int f = 0; f < 8; f++) {
        int colb = n0 + (f & 3) * 8 + lc;
#pragma unroll
        for (int hp = 0; hp < 2; hp++) {
            int row = m0 + (f >> 2) * 16 + lr + hp * 8;
            __half H0, L0, H1, L1;
            wsplit(acc[f][hp * 2], H0, L0); wsplit(acc[f][hp * 2 + 1], H1, L1);
            size_t go = (size_t)(row0 + row) * 128 + colb;
            *(__half2*)(oh + go) = __halves2half2(H0, H1);
            *(__half2*)(ol + go) = __halves2half2(L0, L1);
        }
    }
}

// ===================== grucomb: frat GRU + comb (hF stays on-chip) =====================
__global__ __launch_bounds__(256, 2)
void grucomb_k(const __half* __restrict__ xh, const __half* __restrict__ xl,
               const __half* __restrict__ hh, const __half* __restrict__ hl,
               const __half* __restrict__ whT, const __half* __restrict__ wiT,
               const float* __restrict__ bi, const float* __restrict__ bhp,
               const __half* __restrict__ pah, const __half* __restrict__ pal,
               const __half* __restrict__ ufT, const __half* __restrict__ uaT,
               const float* __restrict__ ufb, const float* __restrict__ uab,
               __half* __restrict__ oh, __half* __restrict__ ol)
{
    extern __shared__ char dsm[];
    const u32 S = smaddr(dsm);
    const int tid = threadIdx.x, lane = tid & 31, wid = tid >> 5;
    const int row0 = blockIdx.x * 64;
    const int m0 = (wid & 1) * 32, n0 = (wid >> 1) * 32;

    load_bias(dsm, bi, bhp, tid);
    stage128(S + oAH, hh + (size_t)row0 * 128, 64, tid, 256);
    stage128(S + oAL, hl + (size_t)row0 * 128, 64, tid, 256);
    stage32s(S + oAXH, xh + (size_t)row0 * 32, 64, tid, 256);
    stage32s(S + oAXL, xl + (size_t)row0 * 32, 64, tid, 256);
    stageBh(S + oBH, whT, 128, tid, 256);
    stageBh(S + oBL, whT + 16384, 128, tid, 256);
    stage32s(S + oBXH, wiT, 128, tid, 256);
    stage32s(S + oBXL, wiT + 4096, 128, tid, 256);
    cpcommit();

    float acc[8][4];
    gru_body(dsm, S, whT, wiT, tid, lane, m0, n0, acc);   // acc = hF

    __syncthreads();   // done reading A(h_old) / B

    // hF -> A panels (overwrites old h)
    const int lr = lane >> 2, lc = 2 * (lane & 3);
#pragma unroll
    for (int f = 0; f < 8; f++) {
        int colb = n0 + (f & 3) * 8 + lc;
#pragma unroll
        for (int hp = 0; hp < 2; hp++) {
            int row = m0 + (f >> 2) * 16 + lr + hp * 8;
            __half H0, L0, H1, L1;
            wsplit(acc[f][hp * 2], H0, L0); wsplit(acc[f][hp * 2 + 1], H1, L1);
            u32 aoff = (u32)row * 256u + (u32)((((colb >> 3) ^ (row & 7)) << 4)) + (colb & 7) * 2;
            *(__half2*)(dsm + oAH + aoff) = __halves2half2(H0, H1);
            *(__half2*)(dsm + oAL + aoff) = __halves2half2(L0, L1);
        }
    }
    stageBh(S + oBH, ufT, 128, tid, 256);
    stageBh(S + oBL, ufT + 16384, 128, tid, 256);
    cpcommit(); cpwait0(); __syncthreads();

    // comb phase 1: hF @ uf (halved B)
    zacc8(acc);
    for (int kc = 0; kc < 4; kc++)
        kstep128h(acc, S + oAH, S + oAL, S + oBH, S + oBL, m0, n0, lane, kc, kc);
    __syncthreads();
    stageBh(S + oBH, ufT + 64, 128, tid, 256);
    stageBh(S + oBL, ufT + 16384 + 64, 128, tid, 256);
    cpcommit(); cpwait0(); __syncthreads();
    for (int kc = 4; kc < 8; kc++)
        kstep128h(acc, S + oAH, S + oAL, S + oBH, S + oBL, m0, n0, lane, kc, kc - 4);
    __syncthreads();

    // comb phase 2: parent hA @ ua (accumulate)
    stage128(S + oAH, pah + (size_t)row0 * 128, 64, tid, 256);
    stage128(S + oAL, pal + (size_t)row0 * 128, 64, tid, 256);
    stageBh(S + oBH, uaT, 128, tid, 256);
    stageBh(S + oBL, uaT + 16384, 128, tid, 256);
    cpcommit(); cpwait0(); __syncthreads();
    for (int kc = 0; kc < 4; kc++)
        kstep128h(acc, S + oAH, S + oAL, S + oBH, S + oBL, m0, n0, lane, kc, kc);
    __syncthreads();
    stageBh(S + oBH, uaT + 64, 128, tid, 256);
    stageBh(S + oBL, uaT + 16384 + 64, 128, tid, 256);
    cpcommit(); cpwait0(); __syncthreads();
    for (int kc = 4; kc < 8; kc++)
        kstep128h(acc, S + oAH, S + oAL, S + oBH, S + oBL, m0, n0, lane, kc, kc - 4);

    // epilogue
#pragma unroll
    for (int f = 0; f < 8; f++) {
        int colb = n0 + (f & 3) * 8 + lc;
        float b0 = __ldg(ufb + colb) + __ldg(uab + colb);
        float b1 = __ldg(ufb + colb + 1) + __ldg(uab + colb + 1);
#pragma unroll
        for (int hp = 0; hp < 2; hp++) {
            int row = m0 + (f >> 2) * 16 + lr + hp * 8;
            float o0 = ftanh(acc[f][hp * 2] + b0);
            float o1 = ftanh(acc[f][hp * 2 + 1] + b1);
            __half H0, L0, H1, L1;
            wsplit(o0, H0, L0); wsplit(o1, H1, L1);
            size_t go = (size_t)(row0 + row) * 128 + colb;
            *(__half2*)(oh + go) = __halves2half2(H0, H1);
            *(__half2*)(ol + go) = __halves2half2(L0, L1);
        }
    }
}

// ===================== leaf node (64-row, 2 CTAs/SM) =====================
#define nAH 0
#define nAL 16384
#define nBH 32768
#define nBL 40960
#define nPR 49152
#define NODE_DS 57344

__global__ __launch_bounds__(256, 2)
void node_k(const __half* __restrict__ hh, const __half* __restrict__ hl,
            const __half* __restrict__ h2oT, const float* __restrict__ b,
            float* __restrict__ pred, __half* __restrict__ ph, __half* __restrict__ pl)
{
    extern __shared__ char dsm[];
    const u32 S = smaddr(dsm);
    const int tid = threadIdx.x, lane = tid & 31, wid = tid >> 5;
    const int row0 = blockIdx.x * 64;

    stage128(S + nAH, hh + (size_t)row0 * 128, 64, tid, 256);
    stage128(S + nAL, hl + (size_t)row0 * 128, 64, tid, 256);
    stageBh(S + nBH, h2oT, 32, tid, 256);
    stageBh(S + nBH + 4096, h2oT + 64, 32, tid, 256);
    stageBh(S + nBL, h2oT + 4096, 32, tid, 256);
    stageBh(S + nBL + 4096, h2oT + 4096 + 64, 32, tid, 256);
    cpcommit(); cpwait0(); __syncthreads();

    {
        const int pm0 = (wid & 3) * 16, Gp = wid >> 2;
        float a4[2][4];
#pragma unroll
        for (int f = 0; f < 2; f++)
#pragma unroll
            for (int i = 0; i < 4; i++) a4[f][i] = 0.0f;
        for (int kc = 0; kc < 8; kc++) {
            int half = kc >> 2, kb = kc & 3;
            u32 ahr[4], alr[4], bh[4], bl[4];
            ldmA128(ahr, S + nAH, pm0, lane, kc);
            ldmA128(alr, S + nAL, pm0, lane, kc);
            ldmBh(bh, S + nBH + half * 4096, Gp * 16, lane, kb);
            ldmBh(bl, S + nBL + half * 4096, Gp * 16, lane, kb);
            mmaf(a4[0], ahr, bh);  mmaf(a4[1], ahr, bh + 2);
            mmaf(a4[0], ahr, bl);  mmaf(a4[1], ahr, bl + 2);
            mmaf(a4[0], alr, bh);  mmaf(a4[1], alr, bh + 2);
        }
        const int lr = lane >> 2, lc = 2 * (lane & 3);
#pragma unroll
        for (int f = 0; f < 2; f++)
#pragma unroll
            for (int i = 0; i < 4; i++) {
                int row = pm0 + lr + (i >> 1) * 8;
                int col = Gp * 16 + f * 8 + lc + (i & 1);
                *(float*)(dsm + nPR + (row * 32 + col) * 4) = a4[f][i] + __ldg(b + col);
            }
    }
    __syncthreads();
    if (tid < 64) {
        int row = tid;
        const float* pr = (const float*)(dsm + nPR + row * 128);
        float v[32], mx = -1e30f;
#pragma unroll
        for (int i = 0; i < 32; i++) { v[i] = pr[i]; mx = fmaxf(mx, v[i]); }
        float e[32], sum = 0.0f;
#pragma unroll
        for (int i = 0; i < 32; i++) { e[i] = __expf(v[i] - mx); sum += e[i]; }
        float inv = __fdividef(1.0f, sum);
        size_t go = (size_t)(row0 + row) * 32;
        float4* pg = (float4*)(pred + go);
#pragma unroll
        for (int q = 0; q < 8; q++)
            pg[q] = make_float4(v[4 * q], v[4 * q + 1], v[4 * q + 2], v[4 * q + 3]);
#pragma unroll
        for (int j = 0; j < 16; j++) {
            float p0 = e[2 * j] * inv, p1 = e[2 * j + 1] * inv;
            __half H0, L0, H1, L1;
            wsplit(p0, H0, L0); wsplit(p1, H1, L1);
            *(__half2*)(ph + go + 2 * j) = __halves2half2(H0, H1);
            *(__half2*)(pl + go + 2 * j) = __halves2half2(L0, L1);
        }
    }
}

// ===================== host =====================
namespace {
struct LCtx {
    const __half* wt;
    const float *h2o_b;
    const float *anc_bi, *anc_bh, *frat_bi, *frat_bh;
    const float *ua_b, *uf_b;
    __half *hAh, *hAl, *prh, *prl;
    float* out;
    int idx;
};

void rec(LCtx& c, int L, int d)
{
    size_t hL = (size_t)L * BATCH * HD, hL1 = (size_t)(L + 1) * BATCH * HD;
    size_t pL = (size_t)L * BATCH * OD, pL1 = (size_t)(L + 1) * BATCH * OD;

    if (d == 0) {
        node_k<<<BATCH / 64, 256, NODE_DS>>>(c.hAh + hL, c.hAl + hL,
                                             c.wt + W_H2O, c.h2o_b,
                                             c.out + (size_t)c.idx * BATCH * OD,
                                             c.prh + pL, c.prl + pL);
        c.idx++;
        return;
    }

    nodegru_k<<<BATCH / 64, 256, FUSE_DS>>>(c.hAh + hL, c.hAl + hL,
                                            c.wt + W_H2O, c.h2o_b,
                                            c.out + (size_t)c.idx * BATCH * OD,
                                            c.prh + pL, c.prl + pL,
                                            c.wt + W_ANC_WH, c.wt + W_ANC_WI,
                                            c.anc_bi, c.anc_bh,
                                            c.hAh + hL1, c.hAl + hL1);
    c.idx++;
    rec(c, L + 1, d - 1);

    grucomb_k<<<BATCH / 64, 256, FUSE_DS>>>(c.prh + pL1, c.prl + pL1,
                                            c.hAh + hL1, c.hAl + hL1,
                                            c.wt + W_FRAT_WH, c.wt + W_FRAT_WI,
                                            c.frat_bi, c.frat_bh,
                                            c.hAh + hL, c.hAl + hL,
                                            c.wt + W_UF, c.wt + W_UA,
                                            c.uf_b, c.ua_b,
                                            c.hAh + hL1, c.hAl + hL1);
    rec(c, L + 1, d - 1);
}
} // namespace

extern "C" void kernel_launch(void* const* d_in, const int* in_sizes, int n_in,
                              void* d_out, int out_size)
{
    const float* z       = (const float*)d_in[0];
    const float* z2h_w   = (const float*)d_in[1];
    const float* z2h_b   = (const float*)d_in[2];
    const float* h2o_w   = (const float*)d_in[3];
    const float* h2o_b   = (const float*)d_in[4];
    const float* anc_wi  = (const float*)d_in[5];
    const float* anc_wh  = (const float*)d_in[6];
    const float* anc_bi  = (const float*)d_in[7];
    const float* anc_bh  = (const float*)d_in[8];
    const float* frat_wi = (const float*)d_in[9];
    const float* frat_wh = (const float*)d_in[10];
    const float* frat_bi = (const float*)d_in[11];
    const float* frat_bh = (const float*)d_in[12];
    const float* ua_w    = (const float*)d_in[13];
    const float* ua_b    = (const float*)d_in[14];
    const float* uf_w    = (const float*)d_in[15];
    const float* uf_b    = (const float*)d_in[16];

    cudaFuncSetAttribute(nodegru_k, cudaFuncAttributeMaxDynamicSharedMemorySize, FUSE_DS);
    cudaFuncSetAttribute(grucomb_k, cudaFuncAttributeMaxDynamicSharedMemorySize, FUSE_DS);
    cudaFuncSetAttribute(node_k,    cudaFuncAttributeMaxDynamicSharedMemorySize, NODE_DS);

    __half *wt, *hAh, *hAl, *prh, *prl;
    cudaGetSymbolAddress((void**)&wt, g_wt);
    cudaGetSymbolAddress((void**)&hAh, g_hAh);
    cudaGetSymbolAddress((void**)&hAl, g_hAl);
    cudaGetSymbolAddress((void**)&prh, g_prh);
    cudaGetSymbolAddress((void**)&prl, g_prl);

    k_prep<<<128, 256>>>(anc_wi, anc_wh, frat_wi, frat_wh, uf_w, ua_w, h2o_w);
    init_k<<<BATCH / 16, 128>>>(z, z2h_w, z2h_b, hAh, hAl);

    LCtx c;
    c.wt = wt; c.h2o_b = h2o_b;
    c.anc_bi = anc_bi; c.anc_bh = anc_bh;
    c.frat_bi = frat_bi; c.frat_bh = frat_bh;
    c.ua_b = ua_b; c.uf_b = uf_b;
    c.hAh = hAh; c.hAl = hAl;
    c.prh = prh; c.prl = prl;
    c.out = (float*)d_out;
    c.idx = 0;
    rec(c, 0, DEPTH);
}